// round 1
// baseline (speedup 1.0000x reference)
#include <cuda_runtime.h>
#include <math.h>

#define NC   4096   // cross tokens (64*64)
#define HCC  64
#define HM   128
#define CI   32
#define CC   64
#define BB   4
#define KCH  4      // key chunks for attention parallelism

// ---------------- scratch (device globals; no allocation) ----------------
__device__ float  d_Q[BB*NC*CI];
__device__ float  d_K[BB*NC*CI];
__device__ float  d_V[BB*NC*CI];
__device__ float  d_PACC[KCH*BB*NC*CI];
__device__ float  d_PDEN[KCH*BB*NC];
__device__ float  d_ATT[BB*NC*CI];
__device__ float  d_WOUT[BB*CC*NC];
__device__ double2 d_PART[64*CC];
__device__ float2 d_STAT[CC];

// ---------------- Kernel A: Q/K/V projections (+2x2 avg pool for V) ------
__global__ void qkv_kernel(const float* __restrict__ crossf,
                           const float* __restrict__ mainf,
                           const float* __restrict__ gw, const float* __restrict__ gb,
                           const float* __restrict__ tw, const float* __restrict__ tb,
                           const float* __restrict__ pw, const float* __restrict__ pb) {
    __shared__ float sGW[CI*CC], sTW[CI*CC], sPW[CI*CC];
    int tid = threadIdx.x;
    for (int i = tid; i < CI*CC; i += 256) { sGW[i]=gw[i]; sTW[i]=tw[i]; sPW[i]=pw[i]; }
    __syncthreads();

    int b = blockIdx.y;
    int n = blockIdx.x*256 + tid;

    float accQ[CI], accK[CI], accV[CI];
    #pragma unroll
    for (int ci=0; ci<CI; ci++) { accQ[ci]=gb[ci]; accK[ci]=tb[ci]; accV[ci]=pb[ci]; }

    const float* cbase = crossf + (size_t)b*CC*NC + n;
    int i = n >> 6, j = n & 63;
    const float* mbase = mainf + (size_t)b*CC*HM*HM + (size_t)(2*i)*HM + 2*j;

    for (int c = 0; c < CC; c++) {
        float xv = cbase[(size_t)c*NC];
        const float* mr = mbase + (size_t)c*HM*HM;
        float pv = 0.25f*((mr[0]+mr[1]) + (mr[HM]+mr[HM+1]));
        #pragma unroll
        for (int ci=0; ci<CI; ci++) {
            accQ[ci] = fmaf(sGW[ci*CC+c], xv, accQ[ci]);
            accK[ci] = fmaf(sTW[ci*CC+c], xv, accK[ci]);
            accV[ci] = fmaf(sPW[ci*CC+c], pv, accV[ci]);
        }
    }

    size_t ob = ((size_t)b*NC + n)*CI;
    #pragma unroll
    for (int ci=0; ci<CI; ci+=4) {
        *(float4*)&d_Q[ob+ci] = make_float4(accQ[ci],accQ[ci+1],accQ[ci+2],accQ[ci+3]);
        *(float4*)&d_K[ob+ci] = make_float4(accK[ci],accK[ci+1],accK[ci+2],accK[ci+3]);
        *(float4*)&d_V[ob+ci] = make_float4(accV[ci],accV[ci+1],accV[ci+2],accV[ci+3]);
    }
}

// ---------------- Kernel B: streaming attention over a key chunk ----------
// grid (16, B, KCH), block 256. Thread = one query row; chunk = 1024 keys.
// Logits are small (|s| < ~10) so no max-subtraction is needed; partials merge by sum.
__global__ void attn_kernel() {
    __shared__ float4 Ks[128*8];
    __shared__ float4 Vs[128*8];

    int b = blockIdx.y;
    int z = blockIdx.z;
    int n = blockIdx.x*256 + threadIdx.x;

    const float4* Qp = (const float4*)&d_Q[((size_t)b*NC + n)*CI];
    float4 q[8];
    #pragma unroll
    for (int i=0;i<8;i++) q[i] = Qp[i];

    float acc[CI];
    #pragma unroll
    for (int ci=0; ci<CI; ci++) acc[ci] = 0.f;
    float den = 0.f;

    int k0 = z*1024;
    for (int t = k0; t < k0+1024; t += 128) {
        __syncthreads();
        const float4* Ksrc = (const float4*)&d_K[((size_t)b*NC + t)*CI];
        const float4* Vsrc = (const float4*)&d_V[((size_t)b*NC + t)*CI];
        #pragma unroll
        for (int i=0;i<4;i++) {
            Ks[threadIdx.x + 256*i] = Ksrc[threadIdx.x + 256*i];
            Vs[threadIdx.x + 256*i] = Vsrc[threadIdx.x + 256*i];
        }
        __syncthreads();

        #pragma unroll 4
        for (int m = 0; m < 128; m++) {
            const float4* kr = &Ks[m*8];
            float s0=0.f, s1=0.f, s2=0.f, s3=0.f;
            #pragma unroll
            for (int i=0;i<8;i+=4) {
                float4 k0v = kr[i+0], k1v = kr[i+1], k2v = kr[i+2], k3v = kr[i+3];
                s0 = fmaf(q[i+0].x,k0v.x, fmaf(q[i+0].y,k0v.y, fmaf(q[i+0].z,k0v.z, fmaf(q[i+0].w,k0v.w, s0))));
                s1 = fmaf(q[i+1].x,k1v.x, fmaf(q[i+1].y,k1v.y, fmaf(q[i+1].z,k1v.z, fmaf(q[i+1].w,k1v.w, s1))));
                s2 = fmaf(q[i+2].x,k2v.x, fmaf(q[i+2].y,k2v.y, fmaf(q[i+2].z,k2v.z, fmaf(q[i+2].w,k2v.w, s2))));
                s3 = fmaf(q[i+3].x,k3v.x, fmaf(q[i+3].y,k3v.y, fmaf(q[i+3].z,k3v.z, fmaf(q[i+3].w,k3v.w, s3))));
            }
            float s = (s0+s1) + (s2+s3);
            float p = __expf(s);
            den += p;
            const float4* vr = &Vs[m*8];
            #pragma unroll
            for (int i=0;i<8;i++) {
                float4 v = vr[i];
                acc[4*i+0] = fmaf(p, v.x, acc[4*i+0]);
                acc[4*i+1] = fmaf(p, v.y, acc[4*i+1]);
                acc[4*i+2] = fmaf(p, v.z, acc[4*i+2]);
                acc[4*i+3] = fmaf(p, v.w, acc[4*i+3]);
            }
        }
    }

    size_t idx = (size_t)b*NC + n;
    d_PDEN[(size_t)z*BB*NC + idx] = den;
    size_t ob = ((size_t)z*BB*NC + idx)*CI;
    #pragma unroll
    for (int ci=0; ci<CI; ci+=4)
        *(float4*)&d_PACC[ob+ci] = make_float4(acc[ci],acc[ci+1],acc[ci+2],acc[ci+3]);
}

// ---------------- Kernel B2: merge key-chunk partials ---------------------
__global__ void attn_combine() {
    size_t idx = (size_t)blockIdx.x*256 + threadIdx.x;   // b*NC+n
    float den = 0.f;
    #pragma unroll
    for (int z=0; z<KCH; z++) den += d_PDEN[(size_t)z*BB*NC + idx];
    float inv = 1.f / den;
    #pragma unroll
    for (int ci=0; ci<CI; ci+=4) {
        float4 a = make_float4(0.f,0.f,0.f,0.f);
        #pragma unroll
        for (int z=0; z<KCH; z++) {
            float4 p = *(const float4*)&d_PACC[((size_t)z*BB*NC + idx)*CI + ci];
            a.x += p.x; a.y += p.y; a.z += p.z; a.w += p.w;
        }
        *(float4*)&d_ATT[idx*CI + ci] = make_float4(a.x*inv, a.y*inv, a.z*inv, a.w*inv);
    }
}

// ---------------- Kernel C1: W conv + BN partial stats --------------------
// block (64 co, 4 y); 64 blocks; each y-thread handles 64 positions.
__global__ void wconv_kernel(const float* __restrict__ ww, const float* __restrict__ wb) {
    __shared__ float sWWT[CI*CC];          // transposed [ci][co] -> conflict-free
    __shared__ double red0[4][CC], red1[4][CC];
    int co = threadIdx.x, ty = threadIdx.y;
    int t = ty*64 + co;
    for (int i = t; i < CI*CC; i += 256) {
        int c2 = i >> 5, ci = i & 31;
        sWWT[ci*CC + c2] = ww[i];
    }
    __syncthreads();

    float bias = wb[co];
    double sum = 0.0, sq = 0.0;
    for (int k = 0; k < 64; k++) {
        int pg = blockIdx.x*256 + k*4 + ty;        // global (b*NC+n)
        int b = pg >> 12, n = pg & 4095;
        const float4* ar = (const float4*)&d_ATT[(size_t)pg*CI];
        float s = bias;
        #pragma unroll
        for (int i=0;i<8;i++) {
            float4 a = ar[i];
            s = fmaf(sWWT[(4*i+0)*CC+co], a.x,
                fmaf(sWWT[(4*i+1)*CC+co], a.y,
                fmaf(sWWT[(4*i+2)*CC+co], a.z,
                fmaf(sWWT[(4*i+3)*CC+co], a.w, s))));
        }
        d_WOUT[((size_t)b*CC + co)*NC + n] = s;
        sum += (double)s;
        sq  += (double)s * (double)s;
    }
    red0[ty][co] = sum; red1[ty][co] = sq;
    __syncthreads();
    if (ty == 0) {
        double s = red0[0][co]+red0[1][co]+red0[2][co]+red0[3][co];
        double q = red1[0][co]+red1[1][co]+red1[2][co]+red1[3][co];
        d_PART[blockIdx.x*CC + co] = make_double2(s, q);
    }
}

// ---------------- Kernel C2: finalize BN affine ---------------------------
__global__ void stats_kernel(const float* __restrict__ gamma, const float* __restrict__ beta) {
    int co = threadIdx.x;
    double s = 0.0, q = 0.0;
    for (int bb = 0; bb < 64; bb++) {
        double2 p = d_PART[bb*CC + co];
        s += p.x; q += p.y;
    }
    const double N = (double)(BB*NC);
    double mean = s / N;
    double var  = q / N - mean*mean;
    float rs = rsqrtf((float)var + 1e-5f);
    float a  = gamma[co] * rs;
    d_STAT[co] = make_float2(a, beta[co] - (float)mean * a);
}

// ---------------- Kernel C3: BN + bilinear 2x upsample + residual ---------
__device__ __forceinline__ void lin_coords(int i, float scale, int n_in, int& i0, int& i1, float& f) {
    float src = ((float)i + 0.5f) * scale - 0.5f;
    src = fminf(fmaxf(src, 0.f), (float)(n_in-1));
    i0 = (int)floorf(src);
    i1 = min(i0 + 1, n_in - 1);
    f  = src - (float)i0;
}

__global__ void out_kernel(const float* __restrict__ mainf, float* __restrict__ out) {
    int idx = blockIdx.x*256 + threadIdx.x;     // [B,64,128,128] flat
    int w  = idx & 127;
    int h  = (idx >> 7) & 127;
    int bc = idx >> 14;                          // b*64+co
    int co = bc & 63;

    int h0,h1,w0,w1; float fh,fw;
    lin_coords(h, 0.5f, HCC, h0, h1, fh);
    lin_coords(w, 0.5f, HCC, w0, w1, fw);

    const float* wp = &d_WOUT[(size_t)bc*NC];
    float v00 = wp[h0*HCC + w0], v01 = wp[h0*HCC + w1];
    float v10 = wp[h1*HCC + w0], v11 = wp[h1*HCC + w1];
    float v0 = v00*(1.f-fw) + v01*fw;
    float v1 = v10*(1.f-fw) + v11*fw;
    float v  = v0*(1.f-fh) + v1*fh;

    float2 st = d_STAT[co];
    out[idx] = fmaf(st.x, v, st.y) + mainf[idx];
}

// ---------------- launch ---------------------------------------------------
extern "C" void kernel_launch(void* const* d_in, const int* in_sizes, int n_in,
                              void* d_out, int out_size) {
    const float* mainf = (const float*)d_in[0];
    const float* crossf= (const float*)d_in[1];
    const float* gw    = (const float*)d_in[2];
    const float* gb    = (const float*)d_in[3];
    const float* tw    = (const float*)d_in[4];
    const float* tb    = (const float*)d_in[5];
    const float* pw    = (const float*)d_in[6];
    const float* pb    = (const float*)d_in[7];
    const float* ww    = (const float*)d_in[8];
    const float* wb    = (const float*)d_in[9];
    const float* bng   = (const float*)d_in[10];
    const float* bnb   = (const float*)d_in[11];
    float* out = (float*)d_out;

    qkv_kernel<<<dim3(16, BB), 256>>>(crossf, mainf, gw, gb, tw, tb, pw, pb);
    attn_kernel<<<dim3(16, BB, KCH), 256>>>();
    attn_combine<<<(BB*NC)/256, 256>>>();
    wconv_kernel<<<64, dim3(64,4)>>>(ww, wb);
    stats_kernel<<<1, 64>>>(bng, bnb);
    out_kernel<<<(BB*CC*HM*HM)/256, 256>>>(mainf, out);
}

// round 4
// speedup vs baseline: 2.2332x; 2.2332x over previous
#include <cuda_runtime.h>
#include <math.h>
#include <stdint.h>

#define NC   4096
#define HCC  64
#define HM   128
#define CI   32
#define CC   64
#define BB   4

// ---------------- scratch ----------------
__device__ float  d_Q[BB*NC*CI];
__device__ float  d_K[BB*NC*CI];
__device__ float  d_V[BB*NC*CI];
__device__ float  d_ATT[BB*NC*CI];
__device__ float  d_WOUT[BB*CC*NC];
__device__ float2 d_STAT[CC];

__device__ __forceinline__ float tf32r(float x){
    uint32_t u; asm("cvt.rna.tf32.f32 %0, %1;" : "=r"(u) : "f"(x)); return __uint_as_float(u);
}
__device__ __forceinline__ uint32_t tf32b(float x){
    uint32_t u; asm("cvt.rna.tf32.f32 %0, %1;" : "=r"(u) : "f"(x)); return u;
}
__device__ __forceinline__ void mma8(float* d, const uint32_t* a, uint32_t b0, uint32_t b1){
    asm volatile("mma.sync.aligned.m16n8k8.row.col.f32.tf32.tf32.f32 "
        "{%0,%1,%2,%3}, {%4,%5,%6,%7}, {%8,%9}, {%0,%1,%2,%3};"
        : "+f"(d[0]),"+f"(d[1]),"+f"(d[2]),"+f"(d[3])
        : "r"(a[0]),"r"(a[1]),"r"(a[2]),"r"(a[3]), "r"(b0),"r"(b1));
}

// ---------------- Kernel A: Q/K/V projections (+2x2 avg pool for V) ------
__global__ void qkv_kernel(const float* __restrict__ crossf,
                           const float* __restrict__ mainf,
                           const float* __restrict__ gw, const float* __restrict__ gb,
                           const float* __restrict__ tw, const float* __restrict__ tb,
                           const float* __restrict__ pw, const float* __restrict__ pb) {
    __shared__ float sGW[CI*CC], sTW[CI*CC], sPW[CI*CC];
    int tid = threadIdx.x;
    for (int i = tid; i < CI*CC; i += 128) { sGW[i]=gw[i]; sTW[i]=tw[i]; sPW[i]=pw[i]; }
    __syncthreads();

    int b = blockIdx.y;
    int n = blockIdx.x*128 + tid;

    float accQ[CI], accK[CI], accV[CI];
    #pragma unroll
    for (int ci=0; ci<CI; ci++) { accQ[ci]=gb[ci]; accK[ci]=tb[ci]; accV[ci]=pb[ci]; }

    const float* cbase = crossf + (size_t)b*CC*NC + n;
    int i = n >> 6, j = n & 63;
    const float* mbase = mainf + (size_t)b*CC*HM*HM + (size_t)(2*i)*HM + 2*j;

    for (int c = 0; c < CC; c++) {
        float xv = cbase[(size_t)c*NC];
        const float* mr = mbase + (size_t)c*HM*HM;
        float pv = 0.25f*((mr[0]+mr[1]) + (mr[HM]+mr[HM+1]));
        #pragma unroll
        for (int ci=0; ci<CI; ci++) {
            accQ[ci] = fmaf(sGW[ci*CC+c], xv, accQ[ci]);
            accK[ci] = fmaf(sTW[ci*CC+c], xv, accK[ci]);
            accV[ci] = fmaf(sPW[ci*CC+c], pv, accV[ci]);
        }
    }

    size_t ob = ((size_t)b*NC + n)*CI;
    #pragma unroll
    for (int ci=0; ci<CI; ci+=4) {
        *(float4*)&d_Q[ob+ci] = make_float4(tf32r(accQ[ci]),tf32r(accQ[ci+1]),tf32r(accQ[ci+2]),tf32r(accQ[ci+3]));
        *(float4*)&d_K[ob+ci] = make_float4(tf32r(accK[ci]),tf32r(accK[ci+1]),tf32r(accK[ci+2]),tf32r(accK[ci+3]));
        *(float4*)&d_V[ob+ci] = make_float4(tf32r(accV[ci]),tf32r(accV[ci+1]),tf32r(accV[ci+2]),tf32r(accV[ci+3]));
    }
}

// ---------------- Kernel B: mma.sync tf32 flash attention -----------------
// grid (32, BB), 128 threads (4 warps). Warp w: query rows qt*128+w*32 .. +31.
#define KSTR 36
#define VSTR 40
#define PSTR 36
#define SMEM_ATT ((128*KSTR + 128*VSTR + 4*32*PSTR)*4)

__global__ void __launch_bounds__(128, 1) attn_kernel() {
    extern __shared__ float smem[];
    float* sK = smem;                       // [128][KSTR]
    float* sV = smem + 128*KSTR;            // [128][VSTR]
    float* sP = smem + 128*KSTR + 128*VSTR; // per warp [32][PSTR]

    int tid = threadIdx.x, lane = tid & 31, w = tid >> 5;
    int gid = lane >> 2, tig = lane & 3;    // groupID (row), threadID-in-group
    int b = blockIdx.y, qt = blockIdx.x;

    // ---- load Q fragments (A-layout), kept in registers all kernel ----
    uint32_t qa[2][4][4];                   // [mtile][ktile][reg]
    {
        const float* Qb = d_Q + ((size_t)(b*NC + qt*128 + w*32))*CI;
        #pragma unroll
        for (int mt=0; mt<2; mt++)
        #pragma unroll
        for (int kt=0; kt<4; kt++) {
            int r0 = (mt*16 + gid)*CI, r1 = r0 + 8*CI;
            int c0 = kt*8 + tig, c1 = c0 + 4;
            qa[mt][kt][0] = __float_as_uint(Qb[r0 + c0]);
            qa[mt][kt][1] = __float_as_uint(Qb[r1 + c0]);
            qa[mt][kt][2] = __float_as_uint(Qb[r0 + c1]);
            qa[mt][kt][3] = __float_as_uint(Qb[r1 + c1]);
        }
    }

    float o[2][4][4];
    #pragma unroll
    for (int mt=0;mt<2;mt++)
    #pragma unroll
    for (int nt=0;nt<4;nt++)
    #pragma unroll
    for (int r=0;r<4;r++) o[mt][nt][r] = 0.f;
    float den[2][2] = {{0.f,0.f},{0.f,0.f}};   // [mtile][rowhalf]

    const float* Kg = d_K + (size_t)b*NC*CI;
    const float* Vg = d_V + (size_t)b*NC*CI;
    float* Pw = sP + w*32*PSTR;

    for (int t = 0; t < 32; t++) {
        __syncthreads();
        // cooperative fill: fully-coalesced global reads
        #pragma unroll
        for (int i=0; i<8; i++) {
            int lin = i*128 + tid;          // 1024 float4 = 128 rows x 8
            int row = lin >> 3, q = lin & 7;
            float4 kv = *(const float4*)(Kg + (size_t)(t*128 + row)*CI + q*4);
            float4 vv = *(const float4*)(Vg + (size_t)(t*128 + row)*CI + q*4);
            *(float4*)&sK[row*KSTR + q*4] = kv;
            *(float4*)&sV[row*VSTR + q*4] = vv;
        }
        __syncthreads();

        #pragma unroll
        for (int ch = 0; ch < 4; ch++) {    // 32-key chunks
            // ---- S = Q K^T for 32x32 chunk ----
            float s[2][4][4];
            #pragma unroll
            for (int mt=0;mt<2;mt++)
            #pragma unroll
            for (int nt=0;nt<4;nt++)
            #pragma unroll
            for (int r=0;r<4;r++) s[mt][nt][r] = 0.f;

            #pragma unroll
            for (int kt=0; kt<4; kt++) {
                #pragma unroll
                for (int nt=0; nt<4; nt++) {
                    int key = ch*32 + nt*8 + gid;
                    int ci0 = kt*8 + tig;
                    uint32_t b0 = __float_as_uint(sK[key*KSTR + ci0]);
                    uint32_t b1 = __float_as_uint(sK[key*KSTR + ci0 + 4]);
                    mma8(s[0][nt], qa[0][kt], b0, b1);
                    mma8(s[1][nt], qa[1][kt], b0, b1);
                }
            }

            // ---- exp, denominators, store P (tf32-rounded) ----
            #pragma unroll
            for (int mt=0; mt<2; mt++)
            #pragma unroll
            for (int nt=0; nt<4; nt++) {
                float p0 = __expf(s[mt][nt][0]);
                float p1 = __expf(s[mt][nt][1]);
                float p2 = __expf(s[mt][nt][2]);
                float p3 = __expf(s[mt][nt][3]);
                den[mt][0] += p0 + p1;
                den[mt][1] += p2 + p3;
                float* pr0 = &Pw[(mt*16 + gid)*PSTR + nt*8 + 2*tig];
                *(float2*)pr0          = make_float2(tf32r(p0), tf32r(p1));
                *(float2*)(pr0+8*PSTR) = make_float2(tf32r(p2), tf32r(p3));
            }
            __syncwarp();

            // ---- O += P V ----
            #pragma unroll
            for (int kt2=0; kt2<4; kt2++) {
                uint32_t pa[2][4];
                #pragma unroll
                for (int mt=0; mt<2; mt++) {
                    int r0 = (mt*16 + gid)*PSTR, r1 = r0 + 8*PSTR;
                    int c0 = kt2*8 + tig, c1 = c0 + 4;
                    pa[mt][0] = __float_as_uint(Pw[r0 + c0]);
                    pa[mt][1] = __float_as_uint(Pw[r1 + c0]);
                    pa[mt][2] = __float_as_uint(Pw[r0 + c1]);
                    pa[mt][3] = __float_as_uint(Pw[r1 + c1]);
                }
                #pragma unroll
                for (int nt=0; nt<4; nt++) {
                    int key0 = ch*32 + kt2*8 + tig;
                    int ci0  = nt*8 + gid;
                    uint32_t vb0 = __float_as_uint(sV[key0*VSTR + ci0]);
                    uint32_t vb1 = __float_as_uint(sV[(key0+4)*VSTR + ci0]);
                    mma8(o[0][nt], pa[0], vb0, vb1);
                    mma8(o[1][nt], pa[1], vb0, vb1);
                }
            }
            __syncwarp();
        }
    }

    // ---- reduce denominators across quads (rows are per l/4 group) ----
    #pragma unroll
    for (int mt=0; mt<2; mt++)
    #pragma unroll
    for (int h=0; h<2; h++) {
        float d = den[mt][h];
        d += __shfl_xor_sync(0xFFFFFFFFu, d, 1);
        d += __shfl_xor_sync(0xFFFFFFFFu, d, 2);
        den[mt][h] = d;
    }

    // ---- normalize + store ----
    #pragma unroll
    for (int mt=0; mt<2; mt++) {
        float invA = 1.f / den[mt][0];
        float invB = 1.f / den[mt][1];
        int row0 = qt*128 + w*32 + mt*16 + gid;
        #pragma unroll
        for (int nt=0; nt<4; nt++) {
            int col = nt*8 + 2*tig;
            *(float2*)&d_ATT[((size_t)(b*NC + row0))*CI + col] =
                make_float2(o[mt][nt][0]*invA, o[mt][nt][1]*invA);
            *(float2*)&d_ATT[((size_t)(b*NC + row0 + 8))*CI + col] =
                make_float2(o[mt][nt][2]*invB, o[mt][nt][3]*invB);
        }
    }
}

// ---------------- Kernel C1: W conv ----------------------------
__global__ void wconv_kernel(const float* __restrict__ ww, const float* __restrict__ wb) {
    __shared__ float sW[CI][CC];
    __shared__ float sA[64][CI+1];
    int t = threadIdx.x;
    for (int i = t; i < CI*CC; i += 256) {
        int ci = i & 31, co = i >> 5;
        sW[ci][co] = ww[i];
    }
    int pbase = blockIdx.x * 64;
    for (int i = t; i < 512; i += 256) {
        int pos = i >> 3, q4 = i & 7;
        float4 v = ((const float4*)d_ATT)[(size_t)(pbase + pos)*8 + q4];
        sA[pos][q4*4+0]=v.x; sA[pos][q4*4+1]=v.y; sA[pos][q4*4+2]=v.z; sA[pos][q4*4+3]=v.w;
    }
    __syncthreads();

    int tx = t & 63, cg = t >> 6;
    float a[CI];
    #pragma unroll
    for (int ci=0; ci<CI; ci++) a[ci] = sA[tx][ci];
    int pg = pbase + tx;
    int b = pg >> 12, n = pg & 4095;
    #pragma unroll
    for (int i2 = 0; i2 < 16; i2++) {
        int co = cg*16 + i2;
        float s = wb[co];
        #pragma unroll
        for (int ci=0; ci<CI; ci++) s = fmaf(sW[ci][co], a[ci], s);
        d_WOUT[((size_t)b*CC + co)*NC + n] = s;
    }
}

// ---------------- Kernel C2: BN stats ---------------------------
__global__ void bnstat_kernel(const float* __restrict__ gamma, const float* __restrict__ beta) {
    __shared__ double rs[256], rq[256];
    int co = blockIdx.x, t = threadIdx.x;
    double s = 0.0, q = 0.0;
    for (int b = 0; b < BB; b++) {
        const float* base = d_WOUT + ((size_t)b*CC + co)*NC;
        for (int i = t; i < NC; i += 256) {
            float v = base[i];
            s += (double)v; q += (double)v * (double)v;
        }
    }
    rs[t] = s; rq[t] = q;
    __syncthreads();
    for (int st = 128; st > 0; st >>= 1) {
        if (t < st) { rs[t] += rs[t+st]; rq[t] += rq[t+st]; }
        __syncthreads();
    }
    if (t == 0) {
        const double N = (double)(BB*NC);
        double mean = rs[0] / N;
        double var  = rq[0] / N - mean*mean;
        float rsv = rsqrtf((float)var + 1e-5f);
        float a = gamma[co] * rsv;
        d_STAT[co] = make_float2(a, beta[co] - (float)mean * a);
    }
}

// ---------------- Kernel C3: BN + bilinear upsample + residual ---------
__device__ __forceinline__ void lin_coords(int i, float scale, int n_in, int& i0, int& i1, float& f) {
    float src = ((float)i + 0.5f) * scale - 0.5f;
    src = fminf(fmaxf(src, 0.f), (float)(n_in-1));
    i0 = (int)floorf(src);
    i1 = min(i0 + 1, n_in - 1);
    f  = src - (float)i0;
}

__global__ void out_kernel(const float* __restrict__ mainf, float* __restrict__ out) {
    int idx = blockIdx.x*256 + threadIdx.x;
    int w  = idx & 127;
    int h  = (idx >> 7) & 127;
    int bc = idx >> 14;
    int co = bc & 63;

    int h0,h1,w0,w1; float fh,fw;
    lin_coords(h, 0.5f, HCC, h0, h1, fh);
    lin_coords(w, 0.5f, HCC, w0, w1, fw);

    const float* wp = &d_WOUT[(size_t)bc*NC];
    float v00 = wp[h0*HCC + w0], v01 = wp[h0*HCC + w1];
    float v10 = wp[h1*HCC + w0], v11 = wp[h1*HCC + w1];
    float v0 = v00*(1.f-fw) + v01*fw;
    float v1 = v10*(1.f-fw) + v11*fw;
    float v  = v0*(1.f-fh) + v1*fh;

    float2 st = d_STAT[co];
    out[idx] = fmaf(st.x, v, st.y) + mainf[idx];
}

// ---------------- launch ---------------------------------------------------
extern "C" void kernel_launch(void* const* d_in, const int* in_sizes, int n_in,
                              void* d_out, int out_size) {
    const float* mainf = (const float*)d_in[0];
    const float* crossf= (const float*)d_in[1];
    const float* gw    = (const float*)d_in[2];
    const float* gb    = (const float*)d_in[3];
    const float* tw    = (const float*)d_in[4];
    const float* tb    = (const float*)d_in[5];
    const float* pw    = (const float*)d_in[6];
    const float* pb    = (const float*)d_in[7];
    const float* ww    = (const float*)d_in[8];
    const float* wb    = (const float*)d_in[9];
    const float* bng   = (const float*)d_in[10];
    const float* bnb   = (const float*)d_in[11];
    float* out = (float*)d_out;

    cudaFuncSetAttribute(attn_kernel, cudaFuncAttributeMaxDynamicSharedMemorySize, SMEM_ATT);

    qkv_kernel<<<dim3(32, BB), 128>>>(crossf, mainf, gw, gb, tw, tb, pw, pb);
    attn_kernel<<<dim3(32, BB), 128, SMEM_ATT>>>();
    wconv_kernel<<<256, 256>>>(ww, wb);
    bnstat_kernel<<<64, 256>>>(bng, bnb);
    out_kernel<<<(BB*CC*HM*HM)/256, 256>>>(mainf, out);
}

// round 7
// speedup vs baseline: 2.2823x; 1.0220x over previous
#include <cuda_runtime.h>
#include <math.h>
#include <stdint.h>

#define NC   4096
#define HCC  64
#define HM   128
#define CI   32
#define CC   64
#define BB   4

// ---------------- scratch ----------------
__device__ float  d_Q[BB*NC*CI];
__device__ float  d_K[BB*NC*CI];
__device__ float  d_V[BB*NC*CI];
__device__ float  d_ATT[BB*NC*CI];
__device__ float  d_WOUT[BB*CC*NC];
__device__ double2 d_PART[CC*8];
__device__ float2 d_STAT[CC];

__device__ __forceinline__ float tf32r(float x){
    uint32_t u; asm("cvt.rna.tf32.f32 %0, %1;" : "=r"(u) : "f"(x)); return __uint_as_float(u);
}
__device__ __forceinline__ void mma8(float* d, const uint32_t* a, uint32_t b0, uint32_t b1){
    asm volatile("mma.sync.aligned.m16n8k8.row.col.f32.tf32.tf32.f32 "
        "{%0,%1,%2,%3}, {%4,%5,%6,%7}, {%8,%9}, {%0,%1,%2,%3};"
        : "+f"(d[0]),"+f"(d[1]),"+f"(d[2]),"+f"(d[3])
        : "r"(a[0]),"r"(a[1]),"r"(a[2]),"r"(a[3]), "r"(b0),"r"(b1));
}

// ---------------- Kernel A: Q/K/V projections (+2x2 avg pool for V) ------
__global__ void qkv_kernel(const float* __restrict__ crossf,
                           const float* __restrict__ mainf,
                           const float* __restrict__ gw, const float* __restrict__ gb,
                           const float* __restrict__ tw, const float* __restrict__ tb,
                           const float* __restrict__ pw, const float* __restrict__ pb) {
    __shared__ float sGW[CI*CC], sTW[CI*CC], sPW[CI*CC];
    int tid = threadIdx.x;
    for (int i = tid; i < CI*CC; i += 128) { sGW[i]=gw[i]; sTW[i]=tw[i]; sPW[i]=pw[i]; }
    __syncthreads();

    int b = blockIdx.y;
    int n = blockIdx.x*128 + tid;

    float accQ[CI], accK[CI], accV[CI];
    #pragma unroll
    for (int ci=0; ci<CI; ci++) { accQ[ci]=gb[ci]; accK[ci]=tb[ci]; accV[ci]=pb[ci]; }

    const float* cbase = crossf + (size_t)b*CC*NC + n;
    int i = n >> 6, j = n & 63;
    const float* mbase = mainf + (size_t)b*CC*HM*HM + (size_t)(2*i)*HM + 2*j;

    for (int c = 0; c < CC; c++) {
        float xv = cbase[(size_t)c*NC];
        const float* mr = mbase + (size_t)c*HM*HM;
        float pv = 0.25f*((mr[0]+mr[1]) + (mr[HM]+mr[HM+1]));
        #pragma unroll
        for (int ci=0; ci<CI; ci++) {
            accQ[ci] = fmaf(sGW[ci*CC+c], xv, accQ[ci]);
            accK[ci] = fmaf(sTW[ci*CC+c], xv, accK[ci]);
            accV[ci] = fmaf(sPW[ci*CC+c], pv, accV[ci]);
        }
    }

    size_t ob = ((size_t)b*NC + n)*CI;
    #pragma unroll
    for (int ci=0; ci<CI; ci+=4) {
        *(float4*)&d_Q[ob+ci] = make_float4(tf32r(accQ[ci]),tf32r(accQ[ci+1]),tf32r(accQ[ci+2]),tf32r(accQ[ci+3]));
        *(float4*)&d_K[ob+ci] = make_float4(tf32r(accK[ci]),tf32r(accK[ci+1]),tf32r(accK[ci+2]),tf32r(accK[ci+3]));
        *(float4*)&d_V[ob+ci] = make_float4(tf32r(accV[ci]),tf32r(accV[ci+1]),tf32r(accV[ci+2]),tf32r(accV[ci+3]));
    }
}

// ---------------- Kernel B: mma.sync tf32 flash attention -----------------
// grid (32, BB), 256 threads (8 warps). Warp w: query rows qt*128 + w*16 .. +15.
#define KSTR 36
#define VSTR 40
#define PSTR 36
#define SMEM_ATT ((128*KSTR + 128*VSTR + 8*16*PSTR)*4)

__global__ void __launch_bounds__(256, 1) attn_kernel() {
    extern __shared__ float smem[];
    float* sK = smem;                       // [128][KSTR]
    float* sV = smem + 128*KSTR;            // [128][VSTR]
    float* sP = smem + 128*KSTR + 128*VSTR; // per warp [16][PSTR]

    int tid = threadIdx.x, lane = tid & 31, w = tid >> 5;
    int gid = lane >> 2, tig = lane & 3;
    int b = blockIdx.y, qt = blockIdx.x;

    // ---- load Q fragments (A-layout) ----
    uint32_t qa[4][4];                      // [ktile][reg]
    {
        const float* Qb = d_Q + ((size_t)(b*NC + qt*128 + w*16))*CI;
        #pragma unroll
        for (int kt=0; kt<4; kt++) {
            int r0 = gid*CI, r1 = r0 + 8*CI;
            int c0 = kt*8 + tig, c1 = c0 + 4;
            qa[kt][0] = __float_as_uint(Qb[r0 + c0]);
            qa[kt][1] = __float_as_uint(Qb[r1 + c0]);
            qa[kt][2] = __float_as_uint(Qb[r0 + c1]);
            qa[kt][3] = __float_as_uint(Qb[r1 + c1]);
        }
    }

    float o[4][4];
    #pragma unroll
    for (int nt=0;nt<4;nt++)
    #pragma unroll
    for (int r=0;r<4;r++) o[nt][r] = 0.f;
    float den[2] = {0.f, 0.f};

    const float* Kg = d_K + (size_t)b*NC*CI;
    const float* Vg = d_V + (size_t)b*NC*CI;
    float* Pw = sP + w*16*PSTR;

    for (int t = 0; t < 32; t++) {
        __syncthreads();
        #pragma unroll
        for (int i=0; i<4; i++) {
            int lin = i*256 + tid;          // 1024 float4 = 128 rows x 8
            int row = lin >> 3, q = lin & 7;
            float4 kv = *(const float4*)(Kg + (size_t)(t*128 + row)*CI + q*4);
            float4 vv = *(const float4*)(Vg + (size_t)(t*128 + row)*CI + q*4);
            *(float4*)&sK[row*KSTR + q*4] = kv;
            *(float4*)&sV[row*VSTR + q*4] = vv;
        }
        __syncthreads();

        #pragma unroll
        for (int ch = 0; ch < 4; ch++) {
            // ---- S = Q K^T for 16x32 chunk ----
            float s[4][4];
            #pragma unroll
            for (int nt=0;nt<4;nt++)
            #pragma unroll
            for (int r=0;r<4;r++) s[nt][r] = 0.f;

            #pragma unroll
            for (int kt=0; kt<4; kt++) {
                #pragma unroll
                for (int nt=0; nt<4; nt++) {
                    int key = ch*32 + nt*8 + gid;
                    int ci0 = kt*8 + tig;
                    uint32_t b0 = __float_as_uint(sK[key*KSTR + ci0]);
                    uint32_t b1 = __float_as_uint(sK[key*KSTR + ci0 + 4]);
                    mma8(s[nt], qa[kt], b0, b1);
                }
            }

            // ---- exp, denominators, store P ----
            #pragma unroll
            for (int nt=0; nt<4; nt++) {
                float p0 = __expf(s[nt][0]);
                float p1 = __expf(s[nt][1]);
                float p2 = __expf(s[nt][2]);
                float p3 = __expf(s[nt][3]);
                den[0] += p0 + p1;
                den[1] += p2 + p3;
                float* pr0 = &Pw[gid*PSTR + nt*8 + 2*tig];
                *(float2*)pr0          = make_float2(p0, p1);
                *(float2*)(pr0+8*PSTR) = make_float2(p2, p3);
            }
            __syncwarp();

            // ---- O += P V ----
            #pragma unroll
            for (int kt2=0; kt2<4; kt2++) {
                uint32_t pa[4];
                {
                    int r0 = gid*PSTR, r1 = r0 + 8*PSTR;
                    int c0 = kt2*8 + tig, c1 = c0 + 4;
                    pa[0] = __float_as_uint(Pw[r0 + c0]);
                    pa[1] = __float_as_uint(Pw[r1 + c0]);
                    pa[2] = __float_as_uint(Pw[r0 + c1]);
                    pa[3] = __float_as_uint(Pw[r1 + c1]);
                }
                #pragma unroll
                for (int nt=0; nt<4; nt++) {
                    int key0 = ch*32 + kt2*8 + tig;
                    int ci0  = nt*8 + gid;
                    uint32_t vb0 = __float_as_uint(sV[key0*VSTR + ci0]);
                    uint32_t vb1 = __float_as_uint(sV[(key0+4)*VSTR + ci0]);
                    mma8(o[nt], pa, vb0, vb1);
                }
            }
            __syncwarp();
        }
    }

    // ---- reduce denominators across quads ----
    #pragma unroll
    for (int h=0; h<2; h++) {
        float d = den[h];
        d += __shfl_xor_sync(0xFFFFFFFFu, d, 1);
        d += __shfl_xor_sync(0xFFFFFFFFu, d, 2);
        den[h] = d;
    }

    // ---- normalize + store ----
    {
        float invA = 1.f / den[0];
        float invB = 1.f / den[1];
        int row0 = qt*128 + w*16 + gid;
        #pragma unroll
        for (int nt=0; nt<4; nt++) {
            int col = nt*8 + 2*tig;
            *(float2*)&d_ATT[((size_t)(b*NC + row0))*CI + col] =
                make_float2(o[nt][0]*invA, o[nt][1]*invA);
            *(float2*)&d_ATT[((size_t)(b*NC + row0 + 8))*CI + col] =
                make_float2(o[nt][2]*invB, o[nt][3]*invB);
        }
    }
}

// ---------------- Kernel C1: W conv ----------------------------
__global__ void wconv_kernel(const float* __restrict__ ww, const float* __restrict__ wb) {
    __shared__ float sW[CI][CC];
    __shared__ float sA[64][CI+1];
    int t = threadIdx.x;
    for (int i = t; i < CI*CC; i += 256) {
        int ci = i & 31, co = i >> 5;
        sW[ci][co] = ww[i];
    }
    int pbase = blockIdx.x * 64;
    for (int i = t; i < 512; i += 256) {
        int pos = i >> 3, q4 = i & 7;
        float4 v = ((const float4*)d_ATT)[(size_t)(pbase + pos)*8 + q4];
        sA[pos][q4*4+0]=v.x; sA[pos][q4*4+1]=v.y; sA[pos][q4*4+2]=v.z; sA[pos][q4*4+3]=v.w;
    }
    __syncthreads();

    int tx = t & 63, cg = t >> 6;
    float a[CI];
    #pragma unroll
    for (int ci=0; ci<CI; ci++) a[ci] = sA[tx][ci];
    int pg = pbase + tx;
    int b = pg >> 12, n = pg & 4095;
    #pragma unroll
    for (int i2 = 0; i2 < 16; i2++) {
        int co = cg*16 + i2;
        float s = wb[co];
        #pragma unroll
        for (int ci=0; ci<CI; ci++) s = fmaf(sW[ci][co], a[ci], s);
        d_WOUT[((size_t)b*CC + co)*NC + n] = s;
    }
}

// ---------------- Kernel C2a: BN partial stats (512 blocks) ---------------
__global__ void bnpart_kernel() {
    __shared__ double rs[128], rq[128];
    int co = blockIdx.x, sl = blockIdx.y, t = threadIdx.x;
    int b = sl >> 1, n0 = (sl & 1) * 2048;
    const float* base = d_WOUT + ((size_t)b*CC + co)*NC + n0;
    double s = 0.0, q = 0.0;
    #pragma unroll 4
    for (int i = t; i < 2048; i += 128) {
        float v = base[i];
        s += (double)v; q += (double)v * (double)v;
    }
    rs[t] = s; rq[t] = q;
    __syncthreads();
    for (int st = 64; st > 0; st >>= 1) {
        if (t < st) { rs[t] += rs[t+st]; rq[t] += rq[t+st]; }
        __syncthreads();
    }
    if (t == 0) d_PART[co*8 + sl] = make_double2(rs[0], rq[0]);
}

// ---------------- Kernel C2b: finalize BN affine --------------------------
__global__ void bnfin_kernel(const float* __restrict__ gamma, const float* __restrict__ beta) {
    int co = threadIdx.x;
    double s = 0.0, q = 0.0;
    #pragma unroll
    for (int i = 0; i < 8; i++) {
        double2 p = d_PART[co*8 + i];
        s += p.x; q += p.y;
    }
    const double N = (double)(BB*NC);
    double mean = s / N;
    double var  = q / N - mean*mean;
    float rsv = rsqrtf((float)var + 1e-5f);
    float a = gamma[co] * rsv;
    d_STAT[co] = make_float2(a, beta[co] - (float)mean * a);
}

// ---------------- Kernel C3: BN + bilinear upsample + residual ---------
__device__ __forceinline__ void lin_coords(int i, float scale, int n_in, int& i0, int& i1, float& f) {
    float src = ((float)i + 0.5f) * scale - 0.5f;
    src = fminf(fmaxf(src, 0.f), (float)(n_in-1));
    i0 = (int)floorf(src);
    i1 = min(i0 + 1, n_in - 1);
    f  = src - (float)i0;
}

__global__ void out_kernel(const float* __restrict__ mainf, float* __restrict__ out) {
    int idx = blockIdx.x*256 + threadIdx.x;
    int w  = idx & 127;
    int h  = (idx >> 7) & 127;
    int bc = idx >> 14;
    int co = bc & 63;

    int h0,h1,w0,w1; float fh,fw;
    lin_coords(h, 0.5f, HCC, h0, h1, fh);
    lin_coords(w, 0.5f, HCC, w0, w1, fw);

    const float* wp = &d_WOUT[(size_t)bc*NC];
    float v00 = wp[h0*HCC + w0], v01 = wp[h0*HCC + w1];
    float v10 = wp[h1*HCC + w0], v11 = wp[h1*HCC + w1];
    float v0 = v00*(1.f-fw) + v01*fw;
    float v1 = v10*(1.f-fw) + v11*fw;
    float v  = v0*(1.f-fh) + v1*fh;

    float2 st = d_STAT[co];
    out[idx] = fmaf(st.x, v, st.y) + mainf[idx];
}

// ---------------- launch ---------------------------------------------------
extern "C" void kernel_launch(void* const* d_in, const int* in_sizes, int n_in,
                              void* d_out, int out_size) {
    const float* mainf = (const float*)d_in[0];
    const float* crossf= (const float*)d_in[1];
    const float* gw    = (const float*)d_in[2];
    const float* gb    = (const float*)d_in[3];
    const float* tw    = (const float*)d_in[4];
    const float* tb    = (const float*)d_in[5];
    const float* pw    = (const float*)d_in[6];
    const float* pb    = (const float*)d_in[7];
    const float* ww    = (const float*)d_in[8];
    const float* wb    = (const float*)d_in[9];
    const float* bng   = (const float*)d_in[10];
    const float* bnb   = (const float*)d_in[11];
    float* out = (float*)d_out;

    cudaFuncSetAttribute(attn_kernel, cudaFuncAttributeMaxDynamicSharedMemorySize, SMEM_ATT);

    qkv_kernel<<<dim3(32, BB), 128>>>(crossf, mainf, gw, gb, tw, tb, pw, pb);
    attn_kernel<<<dim3(32, BB), 256, SMEM_ATT>>>();
    wconv_kernel<<<256, 256>>>(ww, wb);
    bnpart_kernel<<<dim3(CC, 8), 128>>>();
    bnfin_kernel<<<1, 64>>>(bng, bnb);
    out_kernel<<<(BB*CC*HM*HM)/256, 256>>>(mainf, out);
}

// round 8
// speedup vs baseline: 2.5935x; 1.1363x over previous
#include <cuda_runtime.h>
#include <math.h>
#include <stdint.h>

#define NC   4096
#define HCC  64
#define HM   128
#define CI   32
#define CC   64
#define BB   4
#define KS   4          // key-split factor

// ---------------- scratch ----------------
__device__ float  d_Q[BB*NC*CI];
__device__ float  d_K[BB*NC*CI];
__device__ float  d_V[BB*NC*CI];
__device__ float  d_PO[KS*BB*NC*CI];   // unnormalized O partials
__device__ float  d_PD[KS*BB*NC];      // denominator partials
__device__ float  d_ATT[BB*NC*CI];
__device__ float  d_WOUT[BB*CC*NC];
__device__ double2 d_PART[CC*BB];
__device__ float2 d_STAT[CC];

__device__ __forceinline__ float tf32r(float x){
    uint32_t u; asm("cvt.rna.tf32.f32 %0, %1;" : "=r"(u) : "f"(x)); return __uint_as_float(u);
}
__device__ __forceinline__ void mma8(float* d, const uint32_t* a, uint32_t b0, uint32_t b1){
    asm volatile("mma.sync.aligned.m16n8k8.row.col.f32.tf32.tf32.f32 "
        "{%0,%1,%2,%3}, {%4,%5,%6,%7}, {%8,%9}, {%0,%1,%2,%3};"
        : "+f"(d[0]),"+f"(d[1]),"+f"(d[2]),"+f"(d[3])
        : "r"(a[0]),"r"(a[1]),"r"(a[2]),"r"(a[3]), "r"(b0),"r"(b1));
}

// ---------------- Kernel A: Q/K/V projections (+2x2 avg pool for V) ------
__global__ void qkv_kernel(const float* __restrict__ crossf,
                           const float* __restrict__ mainf,
                           const float* __restrict__ gw, const float* __restrict__ gb,
                           const float* __restrict__ tw, const float* __restrict__ tb,
                           const float* __restrict__ pw, const float* __restrict__ pb) {
    __shared__ float sGW[CI*CC], sTW[CI*CC], sPW[CI*CC];
    int tid = threadIdx.x;
    for (int i = tid; i < CI*CC; i += 128) { sGW[i]=gw[i]; sTW[i]=tw[i]; sPW[i]=pw[i]; }
    __syncthreads();

    int b = blockIdx.y;
    int n = blockIdx.x*128 + tid;

    float accQ[CI], accK[CI], accV[CI];
    #pragma unroll
    for (int ci=0; ci<CI; ci++) { accQ[ci]=gb[ci]; accK[ci]=tb[ci]; accV[ci]=pb[ci]; }

    const float* cbase = crossf + (size_t)b*CC*NC + n;
    int i = n >> 6, j = n & 63;
    const float* mbase = mainf + (size_t)b*CC*HM*HM + (size_t)(2*i)*HM + 2*j;

    for (int c = 0; c < CC; c++) {
        float xv = cbase[(size_t)c*NC];
        const float* mr = mbase + (size_t)c*HM*HM;
        float pv = 0.25f*((mr[0]+mr[1]) + (mr[HM]+mr[HM+1]));
        #pragma unroll
        for (int ci=0; ci<CI; ci++) {
            accQ[ci] = fmaf(sGW[ci*CC+c], xv, accQ[ci]);
            accK[ci] = fmaf(sTW[ci*CC+c], xv, accK[ci]);
            accV[ci] = fmaf(sPW[ci*CC+c], pv, accV[ci]);
        }
    }

    size_t ob = ((size_t)b*NC + n)*CI;
    #pragma unroll
    for (int ci=0; ci<CI; ci+=4) {
        *(float4*)&d_Q[ob+ci] = make_float4(tf32r(accQ[ci]),tf32r(accQ[ci+1]),tf32r(accQ[ci+2]),tf32r(accQ[ci+3]));
        *(float4*)&d_K[ob+ci] = make_float4(tf32r(accK[ci]),tf32r(accK[ci+1]),tf32r(accK[ci+2]),tf32r(accK[ci+3]));
        *(float4*)&d_V[ob+ci] = make_float4(tf32r(accV[ci]),tf32r(accV[ci+1]),tf32r(accV[ci+2]),tf32r(accV[ci+3]));
    }
}

// ---------------- Kernel B: mma.sync tf32 flash attention (key-split) ----
// grid (32, BB, KS), 128 threads (4 warps). Warp w: rows qt*128 + w*32 .. +31.
// CTA z processes key tiles [z*8, z*8+8), writes unnormalized partials.
#define KSTR 36
#define VSTR 36
#define PSTR 36
#define SMEM_ATT ((128*KSTR + 128*VSTR + 4*32*PSTR)*4)

__global__ void __launch_bounds__(128, 1) attn_kernel() {
    extern __shared__ float smem[];
    float* sK = smem;                       // [128][KSTR]
    float* sV = smem + 128*KSTR;            // [128][VSTR]
    float* sP = smem + 128*KSTR + 128*VSTR; // per warp [32][PSTR]

    int tid = threadIdx.x, lane = tid & 31, w = tid >> 5;
    int gid = lane >> 2, tig = lane & 3;
    int b = blockIdx.y, qt = blockIdx.x, z = blockIdx.z;

    // ---- Q fragments (A-layout), registers all kernel ----
    uint32_t qa[2][4][4];
    {
        const float* Qb = d_Q + ((size_t)(b*NC + qt*128 + w*32))*CI;
        #pragma unroll
        for (int mt=0; mt<2; mt++)
        #pragma unroll
        for (int kt=0; kt<4; kt++) {
            int r0 = (mt*16 + gid)*CI, r1 = r0 + 8*CI;
            int c0 = kt*8 + tig, c1 = c0 + 4;
            qa[mt][kt][0] = __float_as_uint(Qb[r0 + c0]);
            qa[mt][kt][1] = __float_as_uint(Qb[r1 + c0]);
            qa[mt][kt][2] = __float_as_uint(Qb[r0 + c1]);
            qa[mt][kt][3] = __float_as_uint(Qb[r1 + c1]);
        }
    }

    float o[2][4][4];
    #pragma unroll
    for (int mt=0;mt<2;mt++)
    #pragma unroll
    for (int nt=0;nt<4;nt++)
    #pragma unroll
    for (int r=0;r<4;r++) o[mt][nt][r] = 0.f;
    float den[2][2] = {{0.f,0.f},{0.f,0.f}};

    const float* Kg = d_K + (size_t)b*NC*CI;
    const float* Vg = d_V + (size_t)b*NC*CI;
    float* Pw = sP + w*32*PSTR;

    for (int t = z*8; t < z*8 + 8; t++) {
        __syncthreads();
        #pragma unroll
        for (int i=0; i<8; i++) {
            int lin = i*128 + tid;          // 1024 float4 = 128 rows x 8
            int row = lin >> 3, q = lin & 7;
            float4 kv = *(const float4*)(Kg + (size_t)(t*128 + row)*CI + q*4);
            float4 vv = *(const float4*)(Vg + (size_t)(t*128 + row)*CI + q*4);
            *(float4*)&sK[row*KSTR + q*4] = kv;
            *(float4*)&sV[row*VSTR + q*4] = vv;
        }
        __syncthreads();

        #pragma unroll
        for (int ch = 0; ch < 4; ch++) {
            // ---- S = Q K^T for 32x32 chunk ----
            float s[2][4][4];
            #pragma unroll
            for (int mt=0;mt<2;mt++)
            #pragma unroll
            for (int nt=0;nt<4;nt++)
            #pragma unroll
            for (int r=0;r<4;r++) s[mt][nt][r] = 0.f;

            #pragma unroll
            for (int kt=0; kt<4; kt++) {
                #pragma unroll
                for (int nt=0; nt<4; nt++) {
                    int key = ch*32 + nt*8 + gid;
                    int ci0 = kt*8 + tig;
                    uint32_t b0 = __float_as_uint(sK[key*KSTR + ci0]);
                    uint32_t b1 = __float_as_uint(sK[key*KSTR + ci0 + 4]);
                    mma8(s[0][nt], qa[0][kt], b0, b1);
                    mma8(s[1][nt], qa[1][kt], b0, b1);
                }
            }

            // ---- exp, denominators, store P ----
            #pragma unroll
            for (int mt=0; mt<2; mt++)
            #pragma unroll
            for (int nt=0; nt<4; nt++) {
                float p0 = __expf(s[mt][nt][0]);
                float p1 = __expf(s[mt][nt][1]);
                float p2 = __expf(s[mt][nt][2]);
                float p3 = __expf(s[mt][nt][3]);
                den[mt][0] += p0 + p1;
                den[mt][1] += p2 + p3;
                float* pr0 = &Pw[(mt*16 + gid)*PSTR + nt*8 + 2*tig];
                *(float2*)pr0          = make_float2(p0, p1);
                *(float2*)(pr0+8*PSTR) = make_float2(p2, p3);
            }
            __syncwarp();

            // ---- O += P V ----
            #pragma unroll
            for (int kt2=0; kt2<4; kt2++) {
                uint32_t pa[2][4];
                #pragma unroll
                for (int mt=0; mt<2; mt++) {
                    int r0 = (mt*16 + gid)*PSTR, r1 = r0 + 8*PSTR;
                    int c0 = kt2*8 + tig, c1 = c0 + 4;
                    pa[mt][0] = __float_as_uint(Pw[r0 + c0]);
                    pa[mt][1] = __float_as_uint(Pw[r1 + c0]);
                    pa[mt][2] = __float_as_uint(Pw[r0 + c1]);
                    pa[mt][3] = __float_as_uint(Pw[r1 + c1]);
                }
                #pragma unroll
                for (int nt=0; nt<4; nt++) {
                    int key0 = ch*32 + kt2*8 + tig;
                    int ci0  = nt*8 + gid;
                    uint32_t vb0 = __float_as_uint(sV[key0*VSTR + ci0]);
                    uint32_t vb1 = __float_as_uint(sV[(key0+4)*VSTR + ci0]);
                    mma8(o[0][nt], pa[0], vb0, vb1);
                    mma8(o[1][nt], pa[1], vb0, vb1);
                }
            }
            __syncwarp();
        }
    }

    // ---- reduce denominators across quads ----
    #pragma unroll
    for (int mt=0; mt<2; mt++)
    #pragma unroll
    for (int h=0; h<2; h++) {
        float d = den[mt][h];
        d += __shfl_xor_sync(0xFFFFFFFFu, d, 1);
        d += __shfl_xor_sync(0xFFFFFFFFu, d, 2);
        den[mt][h] = d;
    }

    // ---- store unnormalized partials ----
    size_t zb = (size_t)(z*BB + b);
    #pragma unroll
    for (int mt=0; mt<2; mt++) {
        int row0 = qt*128 + w*32 + mt*16 + gid;
        if (tig == 0) {
            d_PD[zb*NC + row0]     = den[mt][0];
            d_PD[zb*NC + row0 + 8] = den[mt][1];
        }
        #pragma unroll
        for (int nt=0; nt<4; nt++) {
            int col = nt*8 + 2*tig;
            *(float2*)&d_PO[(zb*NC + row0)*CI + col] =
                make_float2(o[mt][nt][0], o[mt][nt][1]);
            *(float2*)&d_PO[(zb*NC + row0 + 8)*CI + col] =
                make_float2(o[mt][nt][2], o[mt][nt][3]);
        }
    }
}

// ---------------- Kernel B2: combine key-split partials -------------------
__global__ void attn_combine() {
    int idx = blockIdx.x*256 + threadIdx.x;     // b*NC + n
    float den = 0.f;
    #pragma unroll
    for (int zz=0; zz<KS; zz++) {
        int z = zz, b = idx >> 12;
        den += d_PD[((size_t)(z*BB + b))*NC + (idx & 4095)];
    }
    float inv = 1.f / den;
    int b = idx >> 12, n = idx & 4095;
    #pragma unroll
    for (int c4 = 0; c4 < 8; c4++) {
        float4 a = make_float4(0.f,0.f,0.f,0.f);
        #pragma unroll
        for (int z=0; z<KS; z++) {
            float4 p = *(const float4*)&d_PO[(((size_t)(z*BB + b))*NC + n)*CI + c4*4];
            a.x += p.x; a.y += p.y; a.z += p.z; a.w += p.w;
        }
        *(float4*)&d_ATT[(size_t)idx*CI + c4*4] = make_float4(a.x*inv, a.y*inv, a.z*inv, a.w*inv);
    }
}

// ---------------- Kernel C1: W conv ----------------------------
__global__ void wconv_kernel(const float* __restrict__ ww, const float* __restrict__ wb) {
    __shared__ float sW[CI][CC];
    __shared__ float sA[64][CI+1];
    int t = threadIdx.x;
    for (int i = t; i < CI*CC; i += 256) {
        int ci = i & 31, co = i >> 5;
        sW[ci][co] = ww[i];
    }
    int pbase = blockIdx.x * 64;
    for (int i = t; i < 512; i += 256) {
        int pos = i >> 3, q4 = i & 7;
        float4 v = ((const float4*)d_ATT)[(size_t)(pbase + pos)*8 + q4];
        sA[pos][q4*4+0]=v.x; sA[pos][q4*4+1]=v.y; sA[pos][q4*4+2]=v.z; sA[pos][q4*4+3]=v.w;
    }
    __syncthreads();

    int tx = t & 63, cg = t >> 6;
    float a[CI];
    #pragma unroll
    for (int ci=0; ci<CI; ci++) a[ci] = sA[tx][ci];
    int pg = pbase + tx;
    int b = pg >> 12, n = pg & 4095;
    #pragma unroll
    for (int i2 = 0; i2 < 16; i2++) {
        int co = cg*16 + i2;
        float s = wb[co];
        #pragma unroll
        for (int ci=0; ci<CI; ci++) s = fmaf(sW[ci][co], a[ci], s);
        d_WOUT[((size_t)b*CC + co)*NC + n] = s;
    }
}

// ---------------- Kernel C2a: BN partial stats (fp32 accumulate) ----------
__global__ void bnpart_kernel() {
    __shared__ float rs[256], rq[256];
    int co = blockIdx.x, b = blockIdx.y, t = threadIdx.x;
    const float4* base = (const float4*)(d_WOUT + ((size_t)b*CC + co)*NC);
    float s = 0.f, q = 0.f;
    #pragma unroll
    for (int i = 0; i < 4; i++) {
        float4 v = base[t + 256*i];
        s += (v.x + v.y) + (v.z + v.w);
        q += (v.x*v.x + v.y*v.y) + (v.z*v.z + v.w*v.w);
    }
    rs[t] = s; rq[t] = q;
    __syncthreads();
    for (int st = 128; st > 0; st >>= 1) {
        if (t < st) { rs[t] += rs[t+st]; rq[t] += rq[t+st]; }
        __syncthreads();
    }
    if (t == 0) d_PART[co*BB + b] = make_double2((double)rs[0], (double)rq[0]);
}

// ---------------- Kernel C2b: finalize BN affine --------------------------
__global__ void bnfin_kernel(const float* __restrict__ gamma, const float* __restrict__ beta) {
    int co = threadIdx.x;
    double s = 0.0, q = 0.0;
    #pragma unroll
    for (int i = 0; i < BB; i++) {
        double2 p = d_PART[co*BB + i];
        s += p.x; q += p.y;
    }
    const double N = (double)(BB*NC);
    double mean = s / N;
    double var  = q / N - mean*mean;
    float rsv = rsqrtf((float)var + 1e-5f);
    float a = gamma[co] * rsv;
    d_STAT[co] = make_float2(a, beta[co] - (float)mean * a);
}

// ---------------- Kernel C3: BN + bilinear upsample + residual ---------
__device__ __forceinline__ void lin_coords(int i, float scale, int n_in, int& i0, int& i1, float& f) {
    float src = ((float)i + 0.5f) * scale - 0.5f;
    src = fminf(fmaxf(src, 0.f), (float)(n_in-1));
    i0 = (int)floorf(src);
    i1 = min(i0 + 1, n_in - 1);
    f  = src - (float)i0;
}

__global__ void out_kernel(const float* __restrict__ mainf, float* __restrict__ out) {
    int idx = blockIdx.x*256 + threadIdx.x;
    int w  = idx & 127;
    int h  = (idx >> 7) & 127;
    int bc = idx >> 14;
    int co = bc & 63;

    int h0,h1,w0,w1; float fh,fw;
    lin_coords(h, 0.5f, HCC, h0, h1, fh);
    lin_coords(w, 0.5f, HCC, w0, w1, fw);

    const float* wp = &d_WOUT[(size_t)bc*NC];
    float v00 = wp[h0*HCC + w0], v01 = wp[h0*HCC + w1];
    float v10 = wp[h1*HCC + w0], v11 = wp[h1*HCC + w1];
    float v0 = v00*(1.f-fw) + v01*fw;
    float v1 = v10*(1.f-fw) + v11*fw;
    float v  = v0*(1.f-fh) + v1*fh;

    float2 st = d_STAT[co];
    out[idx] = fmaf(st.x, v, st.y) + mainf[idx];
}

// ---------------- launch ---------------------------------------------------
extern "C" void kernel_launch(void* const* d_in, const int* in_sizes, int n_in,
                              void* d_out, int out_size) {
    const float* mainf = (const float*)d_in[0];
    const float* crossf= (const float*)d_in[1];
    const float* gw    = (const float*)d_in[2];
    const float* gb    = (const float*)d_in[3];
    const float* tw    = (const float*)d_in[4];
    const float* tb    = (const float*)d_in[5];
    const float* pw    = (const float*)d_in[6];
    const float* pb    = (const float*)d_in[7];
    const float* ww    = (const float*)d_in[8];
    const float* wb    = (const float*)d_in[9];
    const float* bng   = (const float*)d_in[10];
    const float* bnb   = (const float*)d_in[11];
    float* out = (float*)d_out;

    cudaFuncSetAttribute(attn_kernel, cudaFuncAttributeMaxDynamicSharedMemorySize, SMEM_ATT);

    qkv_kernel<<<dim3(32, BB), 128>>>(crossf, mainf, gw, gb, tw, tb, pw, pb);
    attn_kernel<<<dim3(32, BB, KS), 128, SMEM_ATT>>>();
    attn_combine<<<(BB*NC)/256, 256>>>();
    wconv_kernel<<<256, 256>>>(ww, wb);
    bnpart_kernel<<<dim3(CC, BB), 256>>>();
    bnfin_kernel<<<1, 64>>>(bng, bnb);
    out_kernel<<<(BB*CC*HM*HM)/256, 256>>>(mainf, out);
}

// round 10
// speedup vs baseline: 3.9141x; 1.5092x over previous
#include <cuda_runtime.h>
#include <cuda_fp16.h>
#include <math.h>
#include <stdint.h>

#define NC   4096
#define HCC  64
#define HM   128
#define CI   32
#define CC   64
#define BB   4
#define KS   4          // key-split factor

// ---------------- scratch ----------------
__device__ __half d_Qh[BB*NC*CI];
__device__ __half d_Kh[BB*NC*CI];
__device__ __half d_Vth[BB*CI*NC];     // transposed: [b][ci][n]
__device__ float  d_PO[KS*BB*NC*CI];   // unnormalized O partials
__device__ float  d_PD[KS*BB*NC];      // denominator partials
__device__ float  d_ATT[BB*NC*CI];
__device__ float  d_WOUT[BB*CC*NC];
__device__ double2 d_PART[CC*BB];
__device__ float2 d_STAT[CC];

__device__ __forceinline__ uint32_t pack2(float a, float b){
    __half2 h = __floats2half2_rn(a, b);
    return *(uint32_t*)&h;
}
__device__ __forceinline__ void mma16(float* d, const uint32_t* a, uint32_t b0, uint32_t b1){
    asm volatile("mma.sync.aligned.m16n8k16.row.col.f32.f16.f16.f32 "
        "{%0,%1,%2,%3}, {%4,%5,%6,%7}, {%8,%9}, {%0,%1,%2,%3};"
        : "+f"(d[0]),"+f"(d[1]),"+f"(d[2]),"+f"(d[3])
        : "r"(a[0]),"r"(a[1]),"r"(a[2]),"r"(a[3]), "r"(b0),"r"(b1));
}

// ---------------- Kernel A: Q/K/V projections (+2x2 avg pool for V) ------
__global__ void qkv_kernel(const float* __restrict__ crossf,
                           const float* __restrict__ mainf,
                           const float* __restrict__ gw, const float* __restrict__ gb,
                           const float* __restrict__ tw, const float* __restrict__ tb,
                           const float* __restrict__ pw, const float* __restrict__ pb) {
    __shared__ float sGW[CI*CC], sTW[CI*CC], sPW[CI*CC];
    int tid = threadIdx.x;
    for (int i = tid; i < CI*CC; i += 128) { sGW[i]=gw[i]; sTW[i]=tw[i]; sPW[i]=pw[i]; }
    __syncthreads();

    int b = blockIdx.y;
    int n = blockIdx.x*128 + tid;

    float accQ[CI], accK[CI], accV[CI];
    #pragma unroll
    for (int ci=0; ci<CI; ci++) { accQ[ci]=gb[ci]; accK[ci]=tb[ci]; accV[ci]=pb[ci]; }

    const float* cbase = crossf + (size_t)b*CC*NC + n;
    int i = n >> 6, j = n & 63;
    const float* mbase = mainf + (size_t)b*CC*HM*HM + (size_t)(2*i)*HM + 2*j;

    for (int c = 0; c < CC; c++) {
        float xv = cbase[(size_t)c*NC];
        const float* mr = mbase + (size_t)c*HM*HM;
        float pv = 0.25f*((mr[0]+mr[1]) + (mr[HM]+mr[HM+1]));
        #pragma unroll
        for (int ci=0; ci<CI; ci++) {
            accQ[ci] = fmaf(sGW[ci*CC+c], xv, accQ[ci]);
            accK[ci] = fmaf(sTW[ci*CC+c], xv, accK[ci]);
            accV[ci] = fmaf(sPW[ci*CC+c], pv, accV[ci]);
        }
    }

    size_t ob = ((size_t)b*NC + n)*CI;
    uint32_t qp[16], kp[16];
    #pragma unroll
    for (int h = 0; h < 16; h++) {
        qp[h] = pack2(accQ[2*h], accQ[2*h+1]);
        kp[h] = pack2(accK[2*h], accK[2*h+1]);
    }
    *(uint4*)&d_Qh[ob]     = make_uint4(qp[0], qp[1], qp[2], qp[3]);
    *(uint4*)&d_Qh[ob+8]   = make_uint4(qp[4], qp[5], qp[6], qp[7]);
    *(uint4*)&d_Qh[ob+16]  = make_uint4(qp[8], qp[9], qp[10],qp[11]);
    *(uint4*)&d_Qh[ob+24]  = make_uint4(qp[12],qp[13],qp[14],qp[15]);
    *(uint4*)&d_Kh[ob]     = make_uint4(kp[0], kp[1], kp[2], kp[3]);
    *(uint4*)&d_Kh[ob+8]   = make_uint4(kp[4], kp[5], kp[6], kp[7]);
    *(uint4*)&d_Kh[ob+16]  = make_uint4(kp[8], kp[9], kp[10],kp[11]);
    *(uint4*)&d_Kh[ob+24]  = make_uint4(kp[12],kp[13],kp[14],kp[15]);
    #pragma unroll
    for (int ci=0; ci<CI; ci++)
        d_Vth[((size_t)b*CI + ci)*NC + n] = __float2half_rn(accV[ci]);
}

// ---------------- Kernel B: fp16 mma flash attention (key-split) ----------
// grid (32, BB, KS), 128 threads (4 warps). Warp w: rows qt*128 + w*32 .. +31.
// CTA z: key tiles [z*8, z*8+8). P stays in registers (FA2 fragment reuse).
#define KSTRh 40    // halves per K row (80 B) -> conflict-free
#define VSTRh 136   // halves per Vt row (272 B) -> conflict-free

__global__ void __launch_bounds__(128, 1) attn_kernel() {
    __shared__ __half sK[128*KSTRh];
    __shared__ __half sVt[32*VSTRh];

    int tid = threadIdx.x, lane = tid & 31, w = tid >> 5;
    int gid = lane >> 2, tig = lane & 3;
    int b = blockIdx.y, qt = blockIdx.x, z = blockIdx.z;

    // ---- Q A-fragments (m16n8k16), registers all kernel ----
    uint32_t qa[2][2][4];                // [mt][kci][reg]
    {
        const __half* Qb = d_Qh + ((size_t)(b*NC + qt*128 + w*32))*CI;
        #pragma unroll
        for (int mt=0; mt<2; mt++)
        #pragma unroll
        for (int kci=0; kci<2; kci++) {
            int r0 = (mt*16 + gid)*CI, r1 = r0 + 8*CI;
            int c0 = kci*16 + 2*tig, c1 = c0 + 8;
            qa[mt][kci][0] = *(const uint32_t*)&Qb[r0 + c0];
            qa[mt][kci][1] = *(const uint32_t*)&Qb[r1 + c0];
            qa[mt][kci][2] = *(const uint32_t*)&Qb[r0 + c1];
            qa[mt][kci][3] = *(const uint32_t*)&Qb[r1 + c1];
        }
    }

    float o[2][4][4];
    #pragma unroll
    for (int mt=0;mt<2;mt++)
    #pragma unroll
    for (int nc=0;nc<4;nc++)
    #pragma unroll
    for (int r=0;r<4;r++) o[mt][nc][r] = 0.f;
    float den[2][2] = {{0.f,0.f},{0.f,0.f}};

    const __half* Kg = d_Kh + (size_t)b*NC*CI;
    const __half* Vg = d_Vth + (size_t)b*CI*NC;

    for (int t = z*8; t < z*8 + 8; t++) {
        __syncthreads();
        // K tile: thread tid loads key row tid (64 B)
        {
            const uint4* src = (const uint4*)(Kg + (size_t)(t*128 + tid)*CI);
            #pragma unroll
            for (int q=0; q<4; q++)
                *(uint4*)&sK[tid*KSTRh + q*8] = src[q];
        }
        // Vt tile: 32 rows (ci) x 128 halves (keys)
        #pragma unroll
        for (int i=0; i<4; i++) {
            int lin = i*128 + tid;
            int row = lin >> 4, q = lin & 15;
            *(uint4*)&sVt[row*VSTRh + q*8] =
                *(const uint4*)(Vg + (size_t)row*NC + t*128 + q*8);
        }
        __syncthreads();

        #pragma unroll
        for (int ch = 0; ch < 8; ch++) {      // 16-key chunks
            // ---- S = Q K^T (32 rows x 16 keys) ----
            float s[2][2][4];                 // [mt][ntk][reg]
            #pragma unroll
            for (int mt=0;mt<2;mt++)
            #pragma unroll
            for (int ntk=0;ntk<2;ntk++)
            #pragma unroll
            for (int r=0;r<4;r++) s[mt][ntk][r] = 0.f;

            #pragma unroll
            for (int kci=0; kci<2; kci++) {
                #pragma unroll
                for (int ntk=0; ntk<2; ntk++) {
                    const __half* kr = &sK[(ch*16 + ntk*8 + gid)*KSTRh + kci*16 + 2*tig];
                    uint32_t b0 = *(const uint32_t*)kr;
                    uint32_t b1 = *(const uint32_t*)(kr + 8);
                    mma16(s[0][ntk], qa[0][kci], b0, b1);
                    mma16(s[1][ntk], qa[1][kci], b0, b1);
                }
            }

            // ---- exp + pack into PV A-fragments (registers only) ----
            uint32_t pa[2][4];
            #pragma unroll
            for (int mt=0; mt<2; mt++) {
                #pragma unroll
                for (int ntk=0; ntk<2; ntk++) {
                    float p0 = __expf(s[mt][ntk][0]);
                    float p1 = __expf(s[mt][ntk][1]);
                    float p2 = __expf(s[mt][ntk][2]);
                    float p3 = __expf(s[mt][ntk][3]);
                    den[mt][0] += p0 + p1;
                    den[mt][1] += p2 + p3;
                    pa[mt][2*ntk]   = pack2(p0, p1);
                    pa[mt][2*ntk+1] = pack2(p2, p3);
                }
            }

            // ---- O += P V ----
            #pragma unroll
            for (int nc=0; nc<4; nc++) {
                const __half* vr = &sVt[(nc*8 + gid)*VSTRh + ch*16 + 2*tig];
                uint32_t vb0 = *(const uint32_t*)vr;
                uint32_t vb1 = *(const uint32_t*)(vr + 8);
                mma16(o[0][nc], pa[0], vb0, vb1);
                mma16(o[1][nc], pa[1], vb0, vb1);
            }
        }
    }

    // ---- reduce denominators across quads ----
    #pragma unroll
    for (int mt=0; mt<2; mt++)
    #pragma unroll
    for (int h=0; h<2; h++) {
        float d = den[mt][h];
        d += __shfl_xor_sync(0xFFFFFFFFu, d, 1);
        d += __shfl_xor_sync(0xFFFFFFFFu, d, 2);
        den[mt][h] = d;
    }

    // ---- store unnormalized partials ----
    size_t zb = (size_t)(z*BB + b);
    #pragma unroll
    for (int mt=0; mt<2; mt++) {
        int row0 = qt*128 + w*32 + mt*16 + gid;
        if (tig == 0) {
            d_PD[zb*NC + row0]     = den[mt][0];
            d_PD[zb*NC + row0 + 8] = den[mt][1];
        }
        #pragma unroll
        for (int nc=0; nc<4; nc++) {
            int col = nc*8 + 2*tig;
            *(float2*)&d_PO[(zb*NC + row0)*CI + col] =
                make_float2(o[mt][nc][0], o[mt][nc][1]);
            *(float2*)&d_PO[(zb*NC + row0 + 8)*CI + col] =
                make_float2(o[mt][nc][2], o[mt][nc][3]);
        }
    }
}

// ---------------- Kernel B2: combine key-split partials -------------------
__global__ void attn_combine() {
    int idx = blockIdx.x*256 + threadIdx.x;     // b*NC + n
    int b = idx >> 12, n = idx & 4095;
    float den = 0.f;
    #pragma unroll
    for (int z=0; z<KS; z++)
        den += d_PD[((size_t)(z*BB + b))*NC + n];
    float inv = 1.f / den;
    #pragma unroll
    for (int c4 = 0; c4 < 8; c4++) {
        float4 a = make_float4(0.f,0.f,0.f,0.f);
        #pragma unroll
        for (int z=0; z<KS; z++) {
            float4 p = *(const float4*)&d_PO[(((size_t)(z*BB + b))*NC + n)*CI + c4*4];
            a.x += p.x; a.y += p.y; a.z += p.z; a.w += p.w;
        }
        *(float4*)&d_ATT[(size_t)idx*CI + c4*4] = make_float4(a.x*inv, a.y*inv, a.z*inv, a.w*inv);
    }
}

// ---------------- Kernel C1: W conv ----------------------------
__global__ void wconv_kernel(const float* __restrict__ ww, const float* __restrict__ wb) {
    __shared__ float sW[CI][CC];
    __shared__ float sA[64][CI+1];
    int t = threadIdx.x;
    for (int i = t; i < CI*CC; i += 256) {
        int ci = i & 31, co = i >> 5;
        sW[ci][co] = ww[i];
    }
    int pbase = blockIdx.x * 64;
    for (int i = t; i < 512; i += 256) {
        int pos = i >> 3, q4 = i & 7;
        float4 v = ((const float4*)d_ATT)[(size_t)(pbase + pos)*8 + q4];
        sA[pos][q4*4+0]=v.x; sA[pos][q4*4+1]=v.y; sA[pos][q4*4+2]=v.z; sA[pos][q4*4+3]=v.w;
    }
    __syncthreads();

    int tx = t & 63, cg = t >> 6;
    float a[CI];
    #pragma unroll
    for (int ci=0; ci<CI; ci++) a[ci] = sA[tx][ci];
    int pg = pbase + tx;
    int b = pg >> 12, n = pg & 4095;
    #pragma unroll
    for (int i2 = 0; i2 < 16; i2++) {
        int co = cg*16 + i2;
        float s = wb[co];
        #pragma unroll
        for (int ci=0; ci<CI; ci++) s = fmaf(sW[ci][co], a[ci], s);
        d_WOUT[((size_t)b*CC + co)*NC + n] = s;
    }
}

// ---------------- Kernel C2a: BN partial stats (fp32 accumulate) ----------
__global__ void bnpart_kernel() {
    __shared__ float rs[256], rq[256];
    int co = blockIdx.x, b = blockIdx.y, t = threadIdx.x;
    const float4* base = (const float4*)(d_WOUT + ((size_t)b*CC + co)*NC);
    float s = 0.f, q = 0.f;
    #pragma unroll
    for (int i = 0; i < 4; i++) {
        float4 v = base[t + 256*i];
        s += (v.x + v.y) + (v.z + v.w);
        q += (v.x*v.x + v.y*v.y) + (v.z*v.z + v.w*v.w);
    }
    rs[t] = s; rq[t] = q;
    __syncthreads();
    for (int st = 128; st > 0; st >>= 1) {
        if (t < st) { rs[t] += rs[t+st]; rq[t] += rq[t+st]; }
        __syncthreads();
    }
    if (t == 0) d_PART[co*BB + b] = make_double2((double)rs[0], (double)rq[0]);
}

// ---------------- Kernel C2b: finalize BN affine --------------------------
__global__ void bnfin_kernel(const float* __restrict__ gamma, const float* __restrict__ beta) {
    int co = threadIdx.x;
    double s = 0.0, q = 0.0;
    #pragma unroll
    for (int i = 0; i < BB; i++) {
        double2 p = d_PART[co*BB + i];
        s += p.x; q += p.y;
    }
    const double N = (double)(BB*NC);
    double mean = s / N;
    double var  = q / N - mean*mean;
    float rsv = rsqrtf((float)var + 1e-5f);
    float a = gamma[co] * rsv;
    d_STAT[co] = make_float2(a, beta[co] - (float)mean * a);
}

// ---------------- Kernel C3: BN + bilinear upsample + residual ---------
__device__ __forceinline__ void lin_coords(int i, float scale, int n_in, int& i0, int& i1, float& f) {
    float src = ((float)i + 0.5f) * scale - 0.5f;
    src = fminf(fmaxf(src, 0.f), (float)(n_in-1));
    i0 = (int)floorf(src);
    i1 = min(i0 + 1, n_in - 1);
    f  = src - (float)i0;
}

__global__ void out_kernel(const float* __restrict__ mainf, float* __restrict__ out) {
    int idx = blockIdx.x*256 + threadIdx.x;
    int w  = idx & 127;
    int h  = (idx >> 7) & 127;
    int bc = idx >> 14;
    int co = bc & 63;

    int h0,h1,w0,w1; float fh,fw;
    lin_coords(h, 0.5f, HCC, h0, h1, fh);
    lin_coords(w, 0.5f, HCC, w0, w1, fw);

    const float* wp = &d_WOUT[(size_t)bc*NC];
    float v00 = wp[h0*HCC + w0], v01 = wp[h0*HCC + w1];
    float v10 = wp[h1*HCC + w0], v11 = wp[h1*HCC + w1];
    float v0 = v00*(1.f-fw) + v01*fw;
    float v1 = v10*(1.f-fw) + v11*fw;
    float v  = v0*(1.f-fh) + v1*fh;

    float2 st = d_STAT[co];
    out[idx] = fmaf(st.x, v, st.y) + mainf[idx];
}

// ---------------- launch ---------------------------------------------------
extern "C" void kernel_launch(void* const* d_in, const int* in_sizes, int n_in,
                              void* d_out, int out_size) {
    const float* mainf = (const float*)d_in[0];
    const float* crossf= (const float*)d_in[1];
    const float* gw    = (const float*)d_in[2];
    const float* gb    = (const float*)d_in[3];
    const float* tw    = (const float*)d_in[4];
    const float* tb    = (const float*)d_in[5];
    const float* pw    = (const float*)d_in[6];
    const float* pb    = (const float*)d_in[7];
    const float* ww    = (const float*)d_in[8];
    const float* wb    = (const float*)d_in[9];
    const float* bng   = (const float*)d_in[10];
    const float* bnb   = (const float*)d_in[11];
    float* out = (float*)d_out;

    qkv_kernel<<<dim3(32, BB), 128>>>(crossf, mainf, gw, gb, tw, tb, pw, pb);
    attn_kernel<<<dim3(32, BB, KS), 128>>>();
    attn_combine<<<(BB*NC)/256, 256>>>();
    wconv_kernel<<<256, 256>>>(ww, wb);
    bnpart_kernel<<<dim3(CC, BB), 256>>>();
    bnfin_kernel<<<1, 64>>>(bng, bnb);
    out_kernel<<<(BB*CC*HM*HM)/256, 256>>>(mainf, out);
}

// round 11
// speedup vs baseline: 4.4809x; 1.1448x over previous
#include <cuda_runtime.h>
#include <cuda_fp16.h>
#include <math.h>
#include <stdint.h>

#define NC   4096
#define HCC  64
#define HM   128
#define CI   32
#define CC   64
#define BB   4
#define KS   4          // key-split factor

// ---------------- scratch ----------------
__device__ __half d_Qh[BB*NC*CI];
__device__ __half d_Kh[BB*NC*CI];
__device__ __half d_Vth[BB*CI*NC];     // transposed: [b][ci][n]
__device__ float  d_PO[KS*BB*NC*CI];   // unnormalized O partials
__device__ float  d_PD[KS*BB*NC];      // denominator partials
__device__ float  d_WOUT[BB*CC*NC];
__device__ double2 d_PART[CC*BB];
__device__ float2 d_STAT[CC];

__device__ __forceinline__ uint32_t pack2(float a, float b){
    __half2 h = __floats2half2_rn(a, b);
    return *(uint32_t*)&h;
}
__device__ __forceinline__ void mma16(float* d, const uint32_t* a, uint32_t b0, uint32_t b1){
    asm volatile("mma.sync.aligned.m16n8k16.row.col.f32.f16.f16.f32 "
        "{%0,%1,%2,%3}, {%4,%5,%6,%7}, {%8,%9}, {%0,%1,%2,%3};"
        : "+f"(d[0]),"+f"(d[1]),"+f"(d[2]),"+f"(d[3])
        : "r"(a[0]),"r"(a[1]),"r"(a[2]),"r"(a[3]), "r"(b0),"r"(b1));
}

// ---------------- Kernel A: Q/K/V projections, 2-way channel split -------
// block (128, 2): y-half accumulates 32 input channels; merged via smem.
__global__ void __launch_bounds__(256) qkv_kernel(
        const float* __restrict__ crossf, const float* __restrict__ mainf,
        const float* __restrict__ gw, const float* __restrict__ gb,
        const float* __restrict__ tw, const float* __restrict__ tb,
        const float* __restrict__ pw, const float* __restrict__ pb) {
    __shared__ float sGW[CI*CC], sTW[CI*CC], sPW[CI*CC];
    __shared__ float sRed[128][CI+1];
    int tx = threadIdx.x, ty = threadIdx.y;
    int tid = ty*128 + tx;
    for (int i = tid; i < CI*CC; i += 256) { sGW[i]=gw[i]; sTW[i]=tw[i]; sPW[i]=pw[i]; }
    __syncthreads();

    int b = blockIdx.y;
    int n = blockIdx.x*128 + tx;

    float accQ[CI], accK[CI], accV[CI];
    #pragma unroll
    for (int ci=0; ci<CI; ci++) { accQ[ci]=0.f; accK[ci]=0.f; accV[ci]=0.f; }

    const float* cbase = crossf + (size_t)b*CC*NC + n;
    int i = n >> 6, j = n & 63;
    const float* mbase = mainf + (size_t)b*CC*HM*HM + (size_t)(2*i)*HM + 2*j;

    int c0 = ty*32;
    for (int c = c0; c < c0+32; c++) {
        float xv = cbase[(size_t)c*NC];
        const float* mr = mbase + (size_t)c*HM*HM;
        float2 m0 = *(const float2*)mr;
        float2 m1 = *(const float2*)(mr + HM);
        float pv = 0.25f*((m0.x + m0.y) + (m1.x + m1.y));
        #pragma unroll
        for (int ci=0; ci<CI; ci++) {
            accQ[ci] = fmaf(sGW[ci*CC+c], xv, accQ[ci]);
            accK[ci] = fmaf(sTW[ci*CC+c], xv, accK[ci]);
            accV[ci] = fmaf(sPW[ci*CC+c], pv, accV[ci]);
        }
    }

    // ---- merge halves: Q, K, V rounds through smem ----
    __syncthreads();
    if (ty == 1) {
        #pragma unroll
        for (int ci=0; ci<CI; ci++) sRed[tx][ci] = accQ[ci];
    }
    __syncthreads();
    if (ty == 0) {
        #pragma unroll
        for (int ci=0; ci<CI; ci++) accQ[ci] += sRed[tx][ci] + gb[ci];
    }
    __syncthreads();
    if (ty == 1) {
        #pragma unroll
        for (int ci=0; ci<CI; ci++) sRed[tx][ci] = accK[ci];
    }
    __syncthreads();
    if (ty == 0) {
        #pragma unroll
        for (int ci=0; ci<CI; ci++) accK[ci] += sRed[tx][ci] + tb[ci];
    }
    __syncthreads();
    if (ty == 1) {
        #pragma unroll
        for (int ci=0; ci<CI; ci++) sRed[tx][ci] = accV[ci];
    }
    __syncthreads();
    if (ty == 0) {
        #pragma unroll
        for (int ci=0; ci<CI; ci++) accV[ci] += sRed[tx][ci] + pb[ci];

        size_t ob = ((size_t)b*NC + n)*CI;
        uint32_t qp[16], kp[16];
        #pragma unroll
        for (int h = 0; h < 16; h++) {
            qp[h] = pack2(accQ[2*h], accQ[2*h+1]);
            kp[h] = pack2(accK[2*h], accK[2*h+1]);
        }
        *(uint4*)&d_Qh[ob]     = make_uint4(qp[0], qp[1], qp[2], qp[3]);
        *(uint4*)&d_Qh[ob+8]   = make_uint4(qp[4], qp[5], qp[6], qp[7]);
        *(uint4*)&d_Qh[ob+16]  = make_uint4(qp[8], qp[9], qp[10],qp[11]);
        *(uint4*)&d_Qh[ob+24]  = make_uint4(qp[12],qp[13],qp[14],qp[15]);
        *(uint4*)&d_Kh[ob]     = make_uint4(kp[0], kp[1], kp[2], kp[3]);
        *(uint4*)&d_Kh[ob+8]   = make_uint4(kp[4], kp[5], kp[6], kp[7]);
        *(uint4*)&d_Kh[ob+16]  = make_uint4(kp[8], kp[9], kp[10],kp[11]);
        *(uint4*)&d_Kh[ob+24]  = make_uint4(kp[12],kp[13],kp[14],kp[15]);
        #pragma unroll
        for (int ci=0; ci<CI; ci++)
            d_Vth[((size_t)b*CI + ci)*NC + n] = __float2half_rn(accV[ci]);
    }
}

// ---------------- Kernel B: fp16 mma flash attention (key-split) ----------
// grid (32, BB, KS), 128 threads (4 warps). Warp w: rows qt*128 + w*32 .. +31.
#define KSTRh 40    // halves per K row (80 B) -> conflict-free
#define VSTRh 136   // halves per Vt row (272 B) -> conflict-free

__global__ void __launch_bounds__(128, 1) attn_kernel() {
    __shared__ __half sK[128*KSTRh];
    __shared__ __half sVt[32*VSTRh];

    int tid = threadIdx.x, lane = tid & 31, w = tid >> 5;
    int gid = lane >> 2, tig = lane & 3;
    int b = blockIdx.y, qt = blockIdx.x, z = blockIdx.z;

    uint32_t qa[2][2][4];                // [mt][kci][reg]
    {
        const __half* Qb = d_Qh + ((size_t)(b*NC + qt*128 + w*32))*CI;
        #pragma unroll
        for (int mt=0; mt<2; mt++)
        #pragma unroll
        for (int kci=0; kci<2; kci++) {
            int r0 = (mt*16 + gid)*CI, r1 = r0 + 8*CI;
            int c0 = kci*16 + 2*tig, c1 = c0 + 8;
            qa[mt][kci][0] = *(const uint32_t*)&Qb[r0 + c0];
            qa[mt][kci][1] = *(const uint32_t*)&Qb[r1 + c0];
            qa[mt][kci][2] = *(const uint32_t*)&Qb[r0 + c1];
            qa[mt][kci][3] = *(const uint32_t*)&Qb[r1 + c1];
        }
    }

    float o[2][4][4];
    #pragma unroll
    for (int mt=0;mt<2;mt++)
    #pragma unroll
    for (int nc=0;nc<4;nc++)
    #pragma unroll
    for (int r=0;r<4;r++) o[mt][nc][r] = 0.f;
    float den[2][2] = {{0.f,0.f},{0.f,0.f}};

    const __half* Kg = d_Kh + (size_t)b*NC*CI;
    const __half* Vg = d_Vth + (size_t)b*CI*NC;

    for (int t = z*8; t < z*8 + 8; t++) {
        __syncthreads();
        {
            const uint4* src = (const uint4*)(Kg + (size_t)(t*128 + tid)*CI);
            #pragma unroll
            for (int q=0; q<4; q++)
                *(uint4*)&sK[tid*KSTRh + q*8] = src[q];
        }
        #pragma unroll
        for (int i=0; i<4; i++) {
            int lin = i*128 + tid;
            int row = lin >> 4, q = lin & 15;
            *(uint4*)&sVt[row*VSTRh + q*8] =
                *(const uint4*)(Vg + (size_t)row*NC + t*128 + q*8);
        }
        __syncthreads();

        #pragma unroll
        for (int ch = 0; ch < 8; ch++) {
            float s[2][2][4];
            #pragma unroll
            for (int mt=0;mt<2;mt++)
            #pragma unroll
            for (int ntk=0;ntk<2;ntk++)
            #pragma unroll
            for (int r=0;r<4;r++) s[mt][ntk][r] = 0.f;

            #pragma unroll
            for (int kci=0; kci<2; kci++) {
                #pragma unroll
                for (int ntk=0; ntk<2; ntk++) {
                    const __half* kr = &sK[(ch*16 + ntk*8 + gid)*KSTRh + kci*16 + 2*tig];
                    uint32_t b0 = *(const uint32_t*)kr;
                    uint32_t b1 = *(const uint32_t*)(kr + 8);
                    mma16(s[0][ntk], qa[0][kci], b0, b1);
                    mma16(s[1][ntk], qa[1][kci], b0, b1);
                }
            }

            uint32_t pa[2][4];
            #pragma unroll
            for (int mt=0; mt<2; mt++) {
                #pragma unroll
                for (int ntk=0; ntk<2; ntk++) {
                    float p0 = __expf(s[mt][ntk][0]);
                    float p1 = __expf(s[mt][ntk][1]);
                    float p2 = __expf(s[mt][ntk][2]);
                    float p3 = __expf(s[mt][ntk][3]);
                    den[mt][0] += p0 + p1;
                    den[mt][1] += p2 + p3;
                    pa[mt][2*ntk]   = pack2(p0, p1);
                    pa[mt][2*ntk+1] = pack2(p2, p3);
                }
            }

            #pragma unroll
            for (int nc=0; nc<4; nc++) {
                const __half* vr = &sVt[(nc*8 + gid)*VSTRh + ch*16 + 2*tig];
                uint32_t vb0 = *(const uint32_t*)vr;
                uint32_t vb1 = *(const uint32_t*)(vr + 8);
                mma16(o[0][nc], pa[0], vb0, vb1);
                mma16(o[1][nc], pa[1], vb0, vb1);
            }
        }
    }

    #pragma unroll
    for (int mt=0; mt<2; mt++)
    #pragma unroll
    for (int h=0; h<2; h++) {
        float d = den[mt][h];
        d += __shfl_xor_sync(0xFFFFFFFFu, d, 1);
        d += __shfl_xor_sync(0xFFFFFFFFu, d, 2);
        den[mt][h] = d;
    }

    size_t zb = (size_t)(z*BB + b);
    #pragma unroll
    for (int mt=0; mt<2; mt++) {
        int row0 = qt*128 + w*32 + mt*16 + gid;
        if (tig == 0) {
            d_PD[zb*NC + row0]     = den[mt][0];
            d_PD[zb*NC + row0 + 8] = den[mt][1];
        }
        #pragma unroll
        for (int nc=0; nc<4; nc++) {
            int col = nc*8 + 2*tig;
            *(float2*)&d_PO[(zb*NC + row0)*CI + col] =
                make_float2(o[mt][nc][0], o[mt][nc][1]);
            *(float2*)&d_PO[(zb*NC + row0 + 8)*CI + col] =
                make_float2(o[mt][nc][2], o[mt][nc][3]);
        }
    }
}

// ---------------- Kernel C: fused combine + W conv ------------------------
// 128 blocks x 128 threads; thread = one position (b, n).
__global__ void __launch_bounds__(128) cw_kernel(const float* __restrict__ ww,
                                                 const float* __restrict__ wb) {
    __shared__ float sW[CI][CC];       // sW[ci][co]
    int t = threadIdx.x;
    for (int i = t; i < CI*CC; i += 128) {
        int ci = i & 31, co = i >> 5;
        sW[ci][co] = ww[i];
    }
    __syncthreads();

    int idx = blockIdx.x*128 + t;      // b*NC + n
    int b = idx >> 12, n = idx & 4095;

    float den = 0.f;
    #pragma unroll
    for (int z=0; z<KS; z++)
        den += d_PD[((size_t)(z*BB + b))*NC + n];
    float inv = 1.f / den;

    float a[CI];
    #pragma unroll
    for (int c4 = 0; c4 < 8; c4++) {
        float4 acc = make_float4(0.f,0.f,0.f,0.f);
        #pragma unroll
        for (int z=0; z<KS; z++) {
            float4 p = *(const float4*)&d_PO[(((size_t)(z*BB + b))*NC + n)*CI + c4*4];
            acc.x += p.x; acc.y += p.y; acc.z += p.z; acc.w += p.w;
        }
        a[c4*4+0] = acc.x*inv; a[c4*4+1] = acc.y*inv;
        a[c4*4+2] = acc.z*inv; a[c4*4+3] = acc.w*inv;
    }

    float* wout = d_WOUT + (size_t)b*CC*NC + n;
    #pragma unroll
    for (int co = 0; co < CC; co++) {
        float s = wb[co];
        #pragma unroll
        for (int ci=0; ci<CI; ci++) s = fmaf(sW[ci][co], a[ci], s);
        wout[(size_t)co*NC] = s;
    }
}

// ---------------- Kernel C2a: BN partial stats (fp32 accumulate) ----------
__global__ void bnpart_kernel() {
    __shared__ float rs[256], rq[256];
    int co = blockIdx.x, b = blockIdx.y, t = threadIdx.x;
    const float4* base = (const float4*)(d_WOUT + ((size_t)b*CC + co)*NC);
    float s = 0.f, q = 0.f;
    #pragma unroll
    for (int i = 0; i < 4; i++) {
        float4 v = base[t + 256*i];
        s += (v.x + v.y) + (v.z + v.w);
        q += (v.x*v.x + v.y*v.y) + (v.z*v.z + v.w*v.w);
    }
    rs[t] = s; rq[t] = q;
    __syncthreads();
    for (int st = 128; st > 0; st >>= 1) {
        if (t < st) { rs[t] += rs[t+st]; rq[t] += rq[t+st]; }
        __syncthreads();
    }
    if (t == 0) d_PART[co*BB + b] = make_double2((double)rs[0], (double)rq[0]);
}

// ---------------- Kernel C2b: finalize BN affine --------------------------
__global__ void bnfin_kernel(const float* __restrict__ gamma, const float* __restrict__ beta) {
    int co = threadIdx.x;
    double s = 0.0, q = 0.0;
    #pragma unroll
    for (int i = 0; i < BB; i++) {
        double2 p = d_PART[co*BB + i];
        s += p.x; q += p.y;
    }
    const double N = (double)(BB*NC);
    double mean = s / N;
    double var  = q / N - mean*mean;
    float rsv = rsqrtf((float)var + 1e-5f);
    float a = gamma[co] * rsv;
    d_STAT[co] = make_float2(a, beta[co] - (float)mean * a);
}

// ---------------- Kernel C3: BN + bilinear upsample + residual ---------
__device__ __forceinline__ void lin_coords(int i, float scale, int n_in, int& i0, int& i1, float& f) {
    float src = ((float)i + 0.5f) * scale - 0.5f;
    src = fminf(fmaxf(src, 0.f), (float)(n_in-1));
    i0 = (int)floorf(src);
    i1 = min(i0 + 1, n_in - 1);
    f  = src - (float)i0;
}

__global__ void out_kernel(const float* __restrict__ mainf, float* __restrict__ out) {
    int idx = blockIdx.x*256 + threadIdx.x;
    int w  = idx & 127;
    int h  = (idx >> 7) & 127;
    int bc = idx >> 14;
    int co = bc & 63;

    int h0,h1,w0,w1; float fh,fw;
    lin_coords(h, 0.5f, HCC, h0, h1, fh);
    lin_coords(w, 0.5f, HCC, w0, w1, fw);

    const float* wp = &d_WOUT[(size_t)bc*NC];
    float v00 = wp[h0*HCC + w0], v01 = wp[h0*HCC + w1];
    float v10 = wp[h1*HCC + w0], v11 = wp[h1*HCC + w1];
    float v0 = v00*(1.f-fw) + v01*fw;
    float v1 = v10*(1.f-fw) + v11*fw;
    float v  = v0*(1.f-fh) + v1*fh;

    float2 st = d_STAT[co];
    out[idx] = fmaf(st.x, v, st.y) + mainf[idx];
}

// ---------------- launch ---------------------------------------------------
extern "C" void kernel_launch(void* const* d_in, const int* in_sizes, int n_in,
                              void* d_out, int out_size) {
    const float* mainf = (const float*)d_in[0];
    const float* crossf= (const float*)d_in[1];
    const float* gw    = (const float*)d_in[2];
    const float* gb    = (const float*)d_in[3];
    const float* tw    = (const float*)d_in[4];
    const float* tb    = (const float*)d_in[5];
    const float* pw    = (const float*)d_in[6];
    const float* pb    = (const float*)d_in[7];
    const float* ww    = (const float*)d_in[8];
    const float* wb    = (const float*)d_in[9];
    const float* bng   = (const float*)d_in[10];
    const float* bnb   = (const float*)d_in[11];
    float* out = (float*)d_out;

    qkv_kernel<<<dim3(32, BB), dim3(128, 2)>>>(crossf, mainf, gw, gb, tw, tb, pw, pb);
    attn_kernel<<<dim3(32, BB, KS), 128>>>();
    cw_kernel<<<128, 128>>>(ww, wb);
    bnpart_kernel<<<dim3(CC, BB), 256>>>();
    bnfin_kernel<<<1, 64>>>(bng, bnb);
    out_kernel<<<(BB*CC*HM*HM)/256, 256>>>(mainf, out);
}

// round 12
// speedup vs baseline: 4.6691x; 1.0420x over previous
#include <cuda_runtime.h>
#include <cuda_fp16.h>
#include <math.h>
#include <stdint.h>

#define NC   4096
#define HCC  64
#define HM   128
#define CI   32
#define CC   64
#define BB   4
#define KS   4          // key-split factor

// ---------------- scratch ----------------
__device__ __half d_Qh[BB*NC*CI];
__device__ __half d_Kh[BB*NC*CI];
__device__ __half d_Vth[BB*CI*NC];     // transposed: [b][ci][n]
__device__ float  d_PO[KS*BB*NC*CI];   // unnormalized O partials
__device__ float  d_PD[KS*BB*NC];      // denominator partials
__device__ float  d_WOUT[BB*CC*NC];
__device__ double2 d_PART[CC*16];
__device__ float2 d_STAT[CC];

__device__ __forceinline__ uint32_t pack2(float a, float b){
    __half2 h = __floats2half2_rn(a, b);
    return *(uint32_t*)&h;
}
__device__ __forceinline__ void mma16(float* d, const uint32_t* a, uint32_t b0, uint32_t b1){
    asm volatile("mma.sync.aligned.m16n8k16.row.col.f32.f16.f16.f32 "
        "{%0,%1,%2,%3}, {%4,%5,%6,%7}, {%8,%9}, {%0,%1,%2,%3};"
        : "+f"(d[0]),"+f"(d[1]),"+f"(d[2]),"+f"(d[3])
        : "r"(a[0]),"r"(a[1]),"r"(a[2]),"r"(a[3]), "r"(b0),"r"(b1));
}

// ---------------- Kernel A: Q/K/V projections, 2-way channel split -------
// Q is pre-scaled by log2(e) so attention can use ex2 directly.
__global__ void __launch_bounds__(256) qkv_kernel(
        const float* __restrict__ crossf, const float* __restrict__ mainf,
        const float* __restrict__ gw, const float* __restrict__ gb,
        const float* __restrict__ tw, const float* __restrict__ tb,
        const float* __restrict__ pw, const float* __restrict__ pb) {
    __shared__ float sGW[CI*CC], sTW[CI*CC], sPW[CI*CC];
    __shared__ float sRed[128][CI+1];
    int tx = threadIdx.x, ty = threadIdx.y;
    int tid = ty*128 + tx;
    for (int i = tid; i < CI*CC; i += 256) { sGW[i]=gw[i]; sTW[i]=tw[i]; sPW[i]=pw[i]; }
    __syncthreads();

    int b = blockIdx.y;
    int n = blockIdx.x*128 + tx;

    float accQ[CI], accK[CI], accV[CI];
    #pragma unroll
    for (int ci=0; ci<CI; ci++) { accQ[ci]=0.f; accK[ci]=0.f; accV[ci]=0.f; }

    const float* cbase = crossf + (size_t)b*CC*NC + n;
    int i = n >> 6, j = n & 63;
    const float* mbase = mainf + (size_t)b*CC*HM*HM + (size_t)(2*i)*HM + 2*j;

    int c0 = ty*32;
    for (int c = c0; c < c0+32; c++) {
        float xv = cbase[(size_t)c*NC];
        const float* mr = mbase + (size_t)c*HM*HM;
        float2 m0 = *(const float2*)mr;
        float2 m1 = *(const float2*)(mr + HM);
        float pv = 0.25f*((m0.x + m0.y) + (m1.x + m1.y));
        #pragma unroll
        for (int ci=0; ci<CI; ci++) {
            accQ[ci] = fmaf(sGW[ci*CC+c], xv, accQ[ci]);
            accK[ci] = fmaf(sTW[ci*CC+c], xv, accK[ci]);
            accV[ci] = fmaf(sPW[ci*CC+c], pv, accV[ci]);
        }
    }

    __syncthreads();
    if (ty == 1) {
        #pragma unroll
        for (int ci=0; ci<CI; ci++) sRed[tx][ci] = accQ[ci];
    }
    __syncthreads();
    if (ty == 0) {
        #pragma unroll
        for (int ci=0; ci<CI; ci++) accQ[ci] += sRed[tx][ci] + gb[ci];
    }
    __syncthreads();
    if (ty == 1) {
        #pragma unroll
        for (int ci=0; ci<CI; ci++) sRed[tx][ci] = accK[ci];
    }
    __syncthreads();
    if (ty == 0) {
        #pragma unroll
        for (int ci=0; ci<CI; ci++) accK[ci] += sRed[tx][ci] + tb[ci];
    }
    __syncthreads();
    if (ty == 1) {
        #pragma unroll
        for (int ci=0; ci<CI; ci++) sRed[tx][ci] = accV[ci];
    }
    __syncthreads();
    if (ty == 0) {
        #pragma unroll
        for (int ci=0; ci<CI; ci++) accV[ci] += sRed[tx][ci] + pb[ci];

        const float L2E = 1.4426950408889634f;
        size_t ob = ((size_t)b*NC + n)*CI;
        uint32_t qp[16], kp[16];
        #pragma unroll
        for (int h = 0; h < 16; h++) {
            qp[h] = pack2(accQ[2*h]*L2E, accQ[2*h+1]*L2E);
            kp[h] = pack2(accK[2*h], accK[2*h+1]);
        }
        *(uint4*)&d_Qh[ob]     = make_uint4(qp[0], qp[1], qp[2], qp[3]);
        *(uint4*)&d_Qh[ob+8]   = make_uint4(qp[4], qp[5], qp[6], qp[7]);
        *(uint4*)&d_Qh[ob+16]  = make_uint4(qp[8], qp[9], qp[10],qp[11]);
        *(uint4*)&d_Qh[ob+24]  = make_uint4(qp[12],qp[13],qp[14],qp[15]);
        *(uint4*)&d_Kh[ob]     = make_uint4(kp[0], kp[1], kp[2], kp[3]);
        *(uint4*)&d_Kh[ob+8]   = make_uint4(kp[4], kp[5], kp[6], kp[7]);
        *(uint4*)&d_Kh[ob+16]  = make_uint4(kp[8], kp[9], kp[10],kp[11]);
        *(uint4*)&d_Kh[ob+24]  = make_uint4(kp[12],kp[13],kp[14],kp[15]);
        #pragma unroll
        for (int ci=0; ci<CI; ci++)
            d_Vth[((size_t)b*CI + ci)*NC + n] = __float2half_rn(accV[ci]);
    }
}

// ---------------- Kernel B: fp16 mma flash attention (key-split) ----------
// grid (32, BB, KS), 128 threads (4 warps). Warp w: rows qt*128 + w*32 .. +31.
// exp via ex2.approx.f16x2 (Q pre-scaled by log2e); den via ones-MMA.
#define KSTRh 40    // halves per K row (80 B) -> conflict-free
#define VSTRh 136   // halves per Vt row (272 B) -> conflict-free

__global__ void __launch_bounds__(128, 1) attn_kernel() {
    __shared__ __half sK[128*KSTRh];
    __shared__ __half sVt[32*VSTRh];

    int tid = threadIdx.x, lane = tid & 31, w = tid >> 5;
    int gid = lane >> 2, tig = lane & 3;
    int b = blockIdx.y, qt = blockIdx.x, z = blockIdx.z;
    const uint32_t ONES = 0x3C003C00u;   // (1.0h, 1.0h)

    uint32_t qa[2][2][4];                // [mt][kci][reg]
    {
        const __half* Qb = d_Qh + ((size_t)(b*NC + qt*128 + w*32))*CI;
        #pragma unroll
        for (int mt=0; mt<2; mt++)
        #pragma unroll
        for (int kci=0; kci<2; kci++) {
            int r0 = (mt*16 + gid)*CI, r1 = r0 + 8*CI;
            int c0 = kci*16 + 2*tig, c1 = c0 + 8;
            qa[mt][kci][0] = *(const uint32_t*)&Qb[r0 + c0];
            qa[mt][kci][1] = *(const uint32_t*)&Qb[r1 + c0];
            qa[mt][kci][2] = *(const uint32_t*)&Qb[r0 + c1];
            qa[mt][kci][3] = *(const uint32_t*)&Qb[r1 + c1];
        }
    }

    float o[2][4][4];
    #pragma unroll
    for (int mt=0;mt<2;mt++)
    #pragma unroll
    for (int nc=0;nc<4;nc++)
    #pragma unroll
    for (int r=0;r<4;r++) o[mt][nc][r] = 0.f;
    float dacc[2][4];
    #pragma unroll
    for (int mt=0;mt<2;mt++)
    #pragma unroll
    for (int r=0;r<4;r++) dacc[mt][r] = 0.f;

    const __half* Kg = d_Kh + (size_t)b*NC*CI;
    const __half* Vg = d_Vth + (size_t)b*CI*NC;

    for (int t = z*8; t < z*8 + 8; t++) {
        __syncthreads();
        {
            const uint4* src = (const uint4*)(Kg + (size_t)(t*128 + tid)*CI);
            #pragma unroll
            for (int q=0; q<4; q++)
                *(uint4*)&sK[tid*KSTRh + q*8] = src[q];
        }
        #pragma unroll
        for (int i=0; i<4; i++) {
            int lin = i*128 + tid;
            int row = lin >> 4, q = lin & 15;
            *(uint4*)&sVt[row*VSTRh + q*8] =
                *(const uint4*)(Vg + (size_t)row*NC + t*128 + q*8);
        }
        __syncthreads();

        #pragma unroll
        for (int ch = 0; ch < 8; ch++) {
            float s[2][2][4];
            #pragma unroll
            for (int mt=0;mt<2;mt++)
            #pragma unroll
            for (int ntk=0;ntk<2;ntk++)
            #pragma unroll
            for (int r=0;r<4;r++) s[mt][ntk][r] = 0.f;

            #pragma unroll
            for (int kci=0; kci<2; kci++) {
                #pragma unroll
                for (int ntk=0; ntk<2; ntk++) {
                    const __half* kr = &sK[(ch*16 + ntk*8 + gid)*KSTRh + kci*16 + 2*tig];
                    uint32_t b0 = *(const uint32_t*)kr;
                    uint32_t b1 = *(const uint32_t*)(kr + 8);
                    mma16(s[0][ntk], qa[0][kci], b0, b1);
                    mma16(s[1][ntk], qa[1][kci], b0, b1);
                }
            }

            // ---- p = 2^s via half2 MUFU; fragments stay register-resident ----
            uint32_t pa[2][4];
            #pragma unroll
            for (int mt=0; mt<2; mt++) {
                #pragma unroll
                for (int ntk=0; ntk<2; ntk++) {
                    uint32_t h0 = pack2(s[mt][ntk][0], s[mt][ntk][1]);
                    uint32_t h1 = pack2(s[mt][ntk][2], s[mt][ntk][3]);
                    asm("ex2.approx.f16x2 %0, %0;" : "+r"(h0));
                    asm("ex2.approx.f16x2 %0, %0;" : "+r"(h1));
                    pa[mt][2*ntk]   = h0;
                    pa[mt][2*ntk+1] = h1;
                }
                mma16(dacc[mt], pa[mt], ONES, ONES);   // exact fp32 row sums
            }

            #pragma unroll
            for (int nc=0; nc<4; nc++) {
                const __half* vr = &sVt[(nc*8 + gid)*VSTRh + ch*16 + 2*tig];
                uint32_t vb0 = *(const uint32_t*)vr;
                uint32_t vb1 = *(const uint32_t*)(vr + 8);
                mma16(o[0][nc], pa[0], vb0, vb1);
                mma16(o[1][nc], pa[1], vb0, vb1);
            }
        }
    }

    // dacc cols are all identical row sums: reg0 -> row gid, reg2 -> row gid+8
    size_t zb = (size_t)(z*BB + b);
    #pragma unroll
    for (int mt=0; mt<2; mt++) {
        int row0 = qt*128 + w*32 + mt*16 + gid;
        if (tig == 0) {
            d_PD[zb*NC + row0]     = dacc[mt][0];
            d_PD[zb*NC + row0 + 8] = dacc[mt][2];
        }
        #pragma unroll
        for (int nc=0; nc<4; nc++) {
            int col = nc*8 + 2*tig;
            *(float2*)&d_PO[(zb*NC + row0)*CI + col] =
                make_float2(o[mt][nc][0], o[mt][nc][1]);
            *(float2*)&d_PO[(zb*NC + row0 + 8)*CI + col] =
                make_float2(o[mt][nc][2], o[mt][nc][3]);
        }
    }
}

// ---------------- Kernel C: fused combine + W conv ------------------------
__global__ void __launch_bounds__(128) cw_kernel(const float* __restrict__ ww,
                                                 const float* __restrict__ wb) {
    __shared__ float sW[CI][CC];
    int t = threadIdx.x;
    for (int i = t; i < CI*CC; i += 128) {
        int ci = i & 31, co = i >> 5;
        sW[ci][co] = ww[i];
    }
    __syncthreads();

    int idx = blockIdx.x*128 + t;      // b*NC + n
    int b = idx >> 12, n = idx & 4095;

    float den = 0.f;
    #pragma unroll
    for (int z=0; z<KS; z++)
        den += d_PD[((size_t)(z*BB + b))*NC + n];
    float inv = 1.f / den;

    float a[CI];
    #pragma unroll
    for (int c4 = 0; c4 < 8; c4++) {
        float4 acc = make_float4(0.f,0.f,0.f,0.f);
        #pragma unroll
        for (int z=0; z<KS; z++) {
            float4 p = *(const float4*)&d_PO[(((size_t)(z*BB + b))*NC + n)*CI + c4*4];
            acc.x += p.x; acc.y += p.y; acc.z += p.z; acc.w += p.w;
        }
        a[c4*4+0] = acc.x*inv; a[c4*4+1] = acc.y*inv;
        a[c4*4+2] = acc.z*inv; a[c4*4+3] = acc.w*inv;
    }

    float* wout = d_WOUT + (size_t)b*CC*NC + n;
    #pragma unroll
    for (int co = 0; co < CC; co++) {
        float s = wb[co];
        #pragma unroll
        for (int ci=0; ci<CI; ci++) s = fmaf(sW[ci][co], a[ci], s);
        wout[(size_t)co*NC] = s;
    }
}

// ---------------- Kernel C2a: BN partial stats (16 slices/channel) --------
__global__ void bnpart_kernel() {
    __shared__ float rs[128], rq[128];
    int co = blockIdx.x, sl = blockIdx.y, t = threadIdx.x;
    int b = sl >> 2, q4 = sl & 3;
    const float4* base = (const float4*)(d_WOUT + ((size_t)b*CC + co)*NC + q4*1024);
    float4 v0 = base[t], v1 = base[t + 128];
    float s = (v0.x + v0.y) + (v0.z + v0.w) + (v1.x + v1.y) + (v1.z + v1.w);
    float q = (v0.x*v0.x + v0.y*v0.y) + (v0.z*v0.z + v0.w*v0.w)
            + (v1.x*v1.x + v1.y*v1.y) + (v1.z*v1.z + v1.w*v1.w);
    rs[t] = s; rq[t] = q;
    __syncthreads();
    for (int st = 64; st > 0; st >>= 1) {
        if (t < st) { rs[t] += rs[t+st]; rq[t] += rq[t+st]; }
        __syncthreads();
    }
    if (t == 0) d_PART[co*16 + sl] = make_double2((double)rs[0], (double)rq[0]);
}

// ---------------- Kernel C2b: finalize BN affine --------------------------
__global__ void bnfin_kernel(const float* __restrict__ gamma, const float* __restrict__ beta) {
    int co = threadIdx.x;
    double s = 0.0, q = 0.0;
    #pragma unroll
    for (int i = 0; i < 16; i++) {
        double2 p = d_PART[co*16 + i];
        s += p.x; q += p.y;
    }
    const double N = (double)(BB*NC);
    double mean = s / N;
    double var  = q / N - mean*mean;
    float rsv = rsqrtf((float)var + 1e-5f);
    float a = gamma[co] * rsv;
    d_STAT[co] = make_float2(a, beta[co] - (float)mean * a);
}

// ---------------- Kernel C3: BN + bilinear upsample + residual ---------
__device__ __forceinline__ void lin_coords(int i, float scale, int n_in, int& i0, int& i1, float& f) {
    float src = ((float)i + 0.5f) * scale - 0.5f;
    src = fminf(fmaxf(src, 0.f), (float)(n_in-1));
    i0 = (int)floorf(src);
    i1 = min(i0 + 1, n_in - 1);
    f  = src - (float)i0;
}

__global__ void out_kernel(const float* __restrict__ mainf, float* __restrict__ out) {
    int idx = blockIdx.x*256 + threadIdx.x;
    int w  = idx & 127;
    int h  = (idx >> 7) & 127;
    int bc = idx >> 14;
    int co = bc & 63;

    int h0,h1,w0,w1; float fh,fw;
    lin_coords(h, 0.5f, HCC, h0, h1, fh);
    lin_coords(w, 0.5f, HCC, w0, w1, fw);

    const float* wp = &d_WOUT[(size_t)bc*NC];
    float v00 = wp[h0*HCC + w0], v01 = wp[h0*HCC + w1];
    float v10 = wp[h1*HCC + w0], v11 = wp[h1*HCC + w1];
    float v0 = v00*(1.f-fw) + v01*fw;
    float v1 = v10*(1.f-fw) + v11*fw;
    float v  = v0*(1.f-fh) + v1*fh;

    float2 st = d_STAT[co];
    out[idx] = fmaf(st.x, v, st.y) + mainf[idx];
}

// ---------------- launch ---------------------------------------------------
extern "C" void kernel_launch(void* const* d_in, const int* in_sizes, int n_in,
                              void* d_out, int out_size) {
    const float* mainf = (const float*)d_in[0];
    const float* crossf= (const float*)d_in[1];
    const float* gw    = (const float*)d_in[2];
    const float* gb    = (const float*)d_in[3];
    const float* tw    = (const float*)d_in[4];
    const float* tb    = (const float*)d_in[5];
    const float* pw    = (const float*)d_in[6];
    const float* pb    = (const float*)d_in[7];
    const float* ww    = (const float*)d_in[8];
    const float* wb    = (const float*)d_in[9];
    const float* bng   = (const float*)d_in[10];
    const float* bnb   = (const float*)d_in[11];
    float* out = (float*)d_out;

    qkv_kernel<<<dim3(32, BB), dim3(128, 2)>>>(crossf, mainf, gw, gb, tw, tb, pw, pb);
    attn_kernel<<<dim3(32, BB, KS), 128>>>();
    cw_kernel<<<128, 128>>>(ww, wb);
    bnpart_kernel<<<dim3(CC, 16), 128>>>();
    bnfin_kernel<<<1, 64>>>(bng, bnb);
    out_kernel<<<(BB*CC*HM*HM)/256, 256>>>(mainf, out);
}